// round 10
// baseline (speedup 1.0000x reference)
#include <cuda_runtime.h>
#include <cuda_bf16.h>
#include <math.h>
#include <stdint.h>

#define DIM    1024
#define NHEADS 16
#define HDIM   64
#define BATCH  2
#define SEQ    2048
#define MTOT   (BATCH * SEQ)   // 4096

// ---------------- scratch (static device globals; no allocation) ----------------
__device__ unsigned short g_x_hi[MTOT * DIM];
__device__ unsigned short g_x_lo[MTOT * DIM];
__device__ unsigned short g_w_hi[4 * DIM * DIM];   // Wq, Wk, Wv, Wo
__device__ unsigned short g_w_lo[4 * DIM * DIM];
// Q/K/V head-major [B][H][T][D], bf16 hi/lo (Q pre-scaled by 1/8)
__device__ unsigned short g_q_hi[MTOT * DIM];
__device__ unsigned short g_q_lo[MTOT * DIM];
__device__ unsigned short g_k_hi[MTOT * DIM];
__device__ unsigned short g_k_lo[MTOT * DIM];
__device__ unsigned short g_v_hi[MTOT * DIM];
__device__ unsigned short g_v_lo[MTOT * DIM];
// attention output, token-major [MTOT][DIM], bf16 hi/lo
__device__ unsigned short g_o_hi[MTOT * DIM];
__device__ unsigned short g_o_lo[MTOT * DIM];

// ============================================================================
// helpers
// ============================================================================
__device__ __forceinline__ void split1(float v, unsigned short& h, unsigned short& l)
{
    __nv_bfloat16 hb = __float2bfloat16(v);
    h = __bfloat16_as_ushort(hb);
    l = __bfloat16_as_ushort(__float2bfloat16(v - __bfloat162float(hb)));
}
__device__ __forceinline__ void split4(const float4 v, ushort4& h, ushort4& l)
{
    split1(v.x, h.x, l.x);
    split1(v.y, h.y, l.y);
    split1(v.z, h.z, l.z);
    split1(v.w, h.w, l.w);
}
__device__ __forceinline__ uint32_t bf2pack(float a, float b)
{
    __nv_bfloat162 t = __floats2bfloat162_rn(a, b);
    return *reinterpret_cast<uint32_t*>(&t);
}
__device__ __forceinline__ float bfhi(float v)
{
    return __bfloat162float(__float2bfloat16(v));
}

// fused split, 4 independent float4s per thread (MLP=4).
__global__ void split_all_kernel(const float* __restrict__ x,
                                 const float* __restrict__ Wq,
                                 const float* __restrict__ Wk,
                                 const float* __restrict__ Wv,
                                 const float* __restrict__ Wo)
{
    const int blk = blockIdx.x;
    if (blk < 1024) {
        int base = blk * 1024 + threadIdx.x;
#pragma unroll
        for (int j = 0; j < 4; j++) {
            int i = base + j * 256;
            float4 v = ((const float4*)x)[i];
            ushort4 h, l;
            split4(v, h, l);
            ((ushort4*)g_x_hi)[i] = h;
            ((ushort4*)g_x_lo)[i] = l;
        }
    } else {
        int wbase = (blk - 1024) * 1024 + threadIdx.x;
#pragma unroll
        for (int j = 0; j < 4; j++) {
            int widx = wbase + j * 256;
            int z = widx >> 18;
            int i = widx & 262143;
            const float* w = (z == 0) ? Wq : (z == 1) ? Wk : (z == 2) ? Wv : Wo;
            float4 v = ((const float4*)w)[i];
            ushort4 h, l;
            split4(v, h, l);
            ((ushort4*)g_w_hi)[(size_t)z * 262144 + i] = h;
            ((ushort4*)g_w_lo)[(size_t)z * 262144 + i] = l;
        }
    }
}

// ============================================================================
// async / mma primitives
// ============================================================================
__device__ __forceinline__ void cp16(uint32_t dst, const void* src)
{
    asm volatile("cp.async.cg.shared.global [%0], [%1], 16;\n" :: "r"(dst), "l"(src));
}
__device__ __forceinline__ void cp_commit()
{
    asm volatile("cp.async.commit_group;\n");
}
template<int N> __device__ __forceinline__ void cp_wait()
{
    asm volatile("cp.async.wait_group %0;\n" :: "n"(N));
}
__device__ __forceinline__ void ldsm_x4(uint32_t* r, uint32_t addr)
{
    asm volatile("ldmatrix.sync.aligned.m8n8.x4.shared.b16 {%0,%1,%2,%3}, [%4];"
                 : "=r"(r[0]), "=r"(r[1]), "=r"(r[2]), "=r"(r[3]) : "r"(addr));
}
__device__ __forceinline__ void ldsm_x4_t(uint32_t* r, uint32_t addr)
{
    asm volatile("ldmatrix.sync.aligned.m8n8.x4.trans.shared.b16 {%0,%1,%2,%3}, [%4];"
                 : "=r"(r[0]), "=r"(r[1]), "=r"(r[2]), "=r"(r[3]) : "r"(addr));
}
__device__ __forceinline__ void mma_bf16(float* c, const uint32_t* a, const uint32_t* b)
{
    asm volatile("mma.sync.aligned.m16n8k16.row.col.f32.bf16.bf16.f32 "
                 "{%0,%1,%2,%3},{%4,%5,%6,%7},{%8,%9},{%0,%1,%2,%3};"
                 : "+f"(c[0]), "+f"(c[1]), "+f"(c[2]), "+f"(c[3])
                 : "r"(a[0]), "r"(a[1]), "r"(a[2]), "r"(a[3]), "r"(b[0]), "r"(b[1]));
}

// ============================================================================
// bf16x3 tensor-core GEMM:  C[M,N] = A[M,K] * B[N,K]^T
// BM=128, BN=64, BK=64, 128 threads (4 warps: 4m x 1n, warp tile 32x64),
// 2-stage cp.async smem pipeline + 2-deep REGISTER fragment pipeline
// (ldsm for ks+1 overlaps MMAs for ks). 2 CTAs/SM.
// MODE 0: split + scatter into head-major bf16 hi/lo.  MODE 1: fp32 + bias.
// ============================================================================
#define STG_BYTES 49152
#define AH_OFF 0
#define AL_OFF 16384
#define BH_OFF 32768
#define BL_OFF 40960
#define GEMM_SMEM (2 * STG_BYTES)

struct Frags {
    uint32_t ah[2][4];
    uint32_t al[2][4];
    uint32_t bh[4][4];
    uint32_t bl[4][4];
};

template<int MODE>
__device__ __forceinline__ void gemm_bf16_body(
    const unsigned short* __restrict__ Ah, const unsigned short* __restrict__ Al,
    const unsigned short* __restrict__ Bh, const unsigned short* __restrict__ Bl,
    float scale,
    unsigned short* __restrict__ Chi, unsigned short* __restrict__ Clo,
    const float* __restrict__ bias, float* __restrict__ C)
{
    extern __shared__ char dsm[];
    const uint32_t sbase = (uint32_t)__cvta_generic_to_shared(dsm);

    const int tid  = threadIdx.x;
    const int bm   = blockIdx.y * 128;
    const int bn   = blockIdx.x * 64;
    const int lane = tid & 31;
    const int wm   = tid >> 5;      // 0..3: 32-row band

    auto load_stage = [&](int s, int k0) {
        const uint32_t sb = sbase + s * STG_BYTES;
#pragma unroll
        for (int t = 0; t < 8; t++) {
            int c   = tid + t * 128;        // 0..1023
            int row = c >> 3, ch = c & 7;
            size_t   gofs = (size_t)(bm + row) * DIM + k0 + ch * 8;
            uint32_t sofs = row * 128 + ((ch ^ (row & 7)) << 4);
            cp16(sb + AH_OFF + sofs, Ah + gofs);
            cp16(sb + AL_OFF + sofs, Al + gofs);
        }
#pragma unroll
        for (int t = 0; t < 4; t++) {
            int c   = tid + t * 128;        // 0..511
            int row = c >> 3, ch = c & 7;
            size_t   gofs = (size_t)(bn + row) * DIM + k0 + ch * 8;
            uint32_t sofs = row * 128 + ((ch ^ (row & 7)) << 4);
            cp16(sb + BH_OFF + sofs, Bh + gofs);
            cp16(sb + BL_OFF + sofs, Bl + gofs);
        }
    };

    float acc[2][8][4];
#pragma unroll
    for (int i = 0; i < 2; i++)
#pragma unroll
        for (int j = 0; j < 8; j++)
#pragma unroll
            for (int k = 0; k < 4; k++) acc[i][j][k] = 0.0f;

    const int a_r = wm * 32 + (lane & 15);                 // + mf*16
    const int a_k = (lane >> 4);
    const int a_x = a_r & 7;
    const int b_r = (lane & 7) + ((lane >> 4) << 3);       // + nf2*16
    const int b_k = (lane >> 3) & 1;

    // fragment loader for one ks step
    auto load_frags = [&](uint32_t sb, int ks, Frags& f) {
#pragma unroll
        for (int mf = 0; mf < 2; mf++) {
            uint32_t off = (a_r + mf * 16) * 128 + ((((ks << 1) | a_k) ^ a_x) << 4);
            ldsm_x4(f.ah[mf], sb + AH_OFF + off);
            ldsm_x4(f.al[mf], sb + AL_OFF + off);
        }
#pragma unroll
        for (int nf2 = 0; nf2 < 4; nf2++) {
            int r = b_r + nf2 * 16;
            uint32_t off = r * 128 + ((((ks << 1) | b_k) ^ (r & 7)) << 4);
            ldsm_x4(f.bh[nf2], sb + BH_OFF + off);
            ldsm_x4(f.bl[nf2], sb + BL_OFF + off);
        }
    };

    auto do_mmas = [&](const Frags& f) {
#pragma unroll
        for (int mf = 0; mf < 2; mf++)
#pragma unroll
            for (int nf = 0; nf < 8; nf++) {
                const uint32_t* bhp = &f.bh[nf >> 1][(nf & 1) * 2];
                const uint32_t* blp = &f.bl[nf >> 1][(nf & 1) * 2];
                mma_bf16(acc[mf][nf], f.ah[mf], bhp);
                mma_bf16(acc[mf][nf], f.al[mf], bhp);
                mma_bf16(acc[mf][nf], f.ah[mf], blp);
            }
    };

    load_stage(0, 0);
    cp_commit();

    Frags fb[2];

    constexpr int NIT = DIM / 64;   // 16
    for (int it = 0; it < NIT; ++it) {
        const int s = it & 1;
        if (it + 1 < NIT) {
            load_stage(s ^ 1, (it + 1) * 64);
            cp_commit();
            cp_wait<1>();
        } else {
            cp_wait<0>();
        }
        __syncthreads();

        const uint32_t sb = sbase + s * STG_BYTES;
        load_frags(sb, 0, fb[0]);
#pragma unroll
        for (int ks = 0; ks < 4; ks++) {
            if (ks < 3) load_frags(sb, ks + 1, fb[(ks + 1) & 1]);
            do_mmas(fb[ks & 1]);
        }
        __syncthreads();
    }

    // epilogue
#pragma unroll
    for (int mf = 0; mf < 2; mf++) {
        const int row0 = bm + wm * 32 + mf * 16 + (lane >> 2);
#pragma unroll
        for (int nf = 0; nf < 8; nf++) {
            const int col = bn + nf * 8 + (lane & 3) * 2;
            if (MODE == 0) {
                const int h = col >> 6, d = col & 63;
#pragma unroll
                for (int half = 0; half < 2; half++) {
                    const int row = row0 + half * 8;
                    const int b = row >> 11, t = row & 2047;
                    const size_t dst = (((size_t)(b * NHEADS + h) * SEQ) + t) * HDIM + d;
                    float f0 = acc[mf][nf][half * 2 + 0] * scale;
                    float f1 = acc[mf][nf][half * 2 + 1] * scale;
                    unsigned short h0, l0, h1, l1;
                    split1(f0, h0, l0);
                    split1(f1, h1, l1);
                    *(ushort2*)(Chi + dst) = make_ushort2(h0, h1);
                    *(ushort2*)(Clo + dst) = make_ushort2(l0, l1);
                }
            } else {
                float b0 = bias[col], b1 = bias[col + 1];
                float2 v0 = make_float2(acc[mf][nf][0] + b0, acc[mf][nf][1] + b1);
                float2 v1 = make_float2(acc[mf][nf][2] + b0, acc[mf][nf][3] + b1);
                *(float2*)(C + (size_t)row0 * DIM + col)       = v0;
                *(float2*)(C + (size_t)(row0 + 8) * DIM + col) = v1;
            }
        }
    }
}

__global__ void __launch_bounds__(128, 2) gemm_qkv_bf16()
{
    const int z = blockIdx.z;
    unsigned short* Chi = (z == 0) ? g_q_hi : (z == 1) ? g_k_hi : g_v_hi;
    unsigned short* Clo = (z == 0) ? g_q_lo : (z == 1) ? g_k_lo : g_v_lo;
    const float scale = (z == 0) ? 0.125f : 1.0f;
    gemm_bf16_body<0>(g_x_hi, g_x_lo,
                      g_w_hi + (size_t)z * DIM * DIM, g_w_lo + (size_t)z * DIM * DIM,
                      scale, Chi, Clo, nullptr, nullptr);
}

__global__ void __launch_bounds__(128, 2) gemm_out_bf16(
    const float* __restrict__ bo, float* __restrict__ out)
{
    gemm_bf16_body<1>(g_o_hi, g_o_lo,
                      g_w_hi + (size_t)3 * DIM * DIM, g_w_lo + (size_t)3 * DIM * DIM,
                      1.0f, nullptr, nullptr, bo, out);
}

// ============================================================================
// Tensor-core flash attention (bf16x3, causal) — exact R8 (BQ=64, 2 CTAs/SM).
// ============================================================================
#define ATT_QH 0
#define ATT_QL 8192
#define ATT_STG0 16384
#define ATT_STG_BYTES 32768
#define ATT_KH 0
#define ATT_KL 8192
#define ATT_VH 16384
#define ATT_VL 24576
#define ATT_SMEM (ATT_STG0 + 2 * ATT_STG_BYTES)   // 81920

#define NEG_INF __int_as_float(0xff800000)

__global__ void __launch_bounds__(128, 1) attn_mma_kernel()
{
    extern __shared__ char dsm[];
    const uint32_t sbase = (uint32_t)__cvta_generic_to_shared(dsm);

    const int tid  = threadIdx.x;
    const int lane = tid & 31;
    const int w    = tid >> 5;
    const int qb   = (gridDim.x - 1) - blockIdx.x;
    const int h    = blockIdx.y;
    const int b    = blockIdx.z;
    const int q0   = qb * 64;

    const size_t head = (size_t)(b * NHEADS + h) * SEQ * HDIM;
    const unsigned short* Qh = g_q_hi + head;
    const unsigned short* Ql = g_q_lo + head;
    const unsigned short* Kh = g_k_hi + head;
    const unsigned short* Kl = g_k_lo + head;
    const unsigned short* Vh = g_v_hi + head;
    const unsigned short* Vl = g_v_lo + head;

#pragma unroll
    for (int t = 0; t < 4; t++) {
        int c = tid + t * 128;
        int row = c >> 3, ch = c & 7;
        size_t   g = (size_t)(q0 + row) * HDIM + ch * 8;
        uint32_t sofs = row * 128 + ((ch ^ (row & 7)) << 4);
        cp16(sbase + ATT_QH + sofs, Qh + g);
        cp16(sbase + ATT_QL + sofs, Ql + g);
    }

    auto load_kv = [&](int s, int k0) {
        const uint32_t st = sbase + ATT_STG0 + s * ATT_STG_BYTES;
#pragma unroll
        for (int t = 0; t < 4; t++) {
            int c = tid + t * 128;
            int row = c >> 3, ch = c & 7;
            size_t   g = (size_t)(k0 + row) * HDIM + ch * 8;
            uint32_t sofs = row * 128 + ((ch ^ (row & 7)) << 4);
            cp16(st + ATT_KH + sofs, Kh + g);
            cp16(st + ATT_KL + sofs, Kl + g);
            cp16(st + ATT_VH + sofs, Vh + g);
            cp16(st + ATT_VL + sofs, Vl + g);
        }
    };

    load_kv(0, 0);
    cp_commit();

    const int a_r = w * 16 + (lane & 15);
    const int a_k = lane >> 4;
    const int a_x = a_r & 7;
    const int k_r = (lane & 7) + ((lane >> 4) << 3);
    const int k_k = (lane >> 3) & 1;
    const int v_r = (lane & 7) + (((lane >> 3) & 1) << 3);
    const int v_c = lane >> 4;

    uint32_t qh[4][4], ql[4][4];

    float m_run[2] = {NEG_INF, NEG_INF};
    float l_run[2] = {0.0f, 0.0f};
    float acc_o[8][4];
#pragma unroll
    for (int i = 0; i < 8; i++)
#pragma unroll
        for (int j = 0; j < 4; j++) acc_o[i][j] = 0.0f;

    const int kmax = qb;
    for (int kb = 0; kb <= kmax; kb++) {
        const int s  = kb & 1;
        const int k0 = kb * 64;
        if (kb + 1 <= kmax) {
            load_kv(s ^ 1, (kb + 1) * 64);
            cp_commit();
            cp_wait<1>();
        } else {
            cp_wait<0>();
        }
        __syncthreads();

        if (kb == 0) {
#pragma unroll
            for (int ks = 0; ks < 4; ks++) {
                uint32_t off = a_r * 128 + ((((ks << 1) | a_k) ^ a_x) << 4);
                ldsm_x4(qh[ks], sbase + ATT_QH + off);
                ldsm_x4(ql[ks], sbase + ATT_QL + off);
            }
        }

        const uint32_t st = sbase + ATT_STG0 + s * ATT_STG_BYTES;

        float s_acc[8][4];
#pragma unroll
        for (int i = 0; i < 8; i++)
#pragma unroll
            for (int j = 0; j < 4; j++) s_acc[i][j] = 0.0f;

#pragma unroll
        for (int ks = 0; ks < 4; ks++) {
            uint32_t bh[4][4], bl[4][4];
#pragma unroll
            for (int nf2 = 0; nf2 < 4; nf2++) {
                int r = k_r + nf2 * 16;
                uint32_t off = r * 128 + ((((ks << 1) | k_k) ^ (r & 7)) << 4);
                ldsm_x4(bh[nf2], st + ATT_KH + off);
                ldsm_x4(bl[nf2], st + ATT_KL + off);
            }
#pragma unroll
            for (int nf = 0; nf < 8; nf++) {
                const uint32_t* bhp = &bh[nf >> 1][(nf & 1) * 2];
                const uint32_t* blp = &bl[nf >> 1][(nf & 1) * 2];
                mma_bf16(s_acc[nf], qh[ks], bhp);
                mma_bf16(s_acc[nf], ql[ks], bhp);
                mma_bf16(s_acc[nf], qh[ks], blp);
            }
        }

        if (kb == qb) {
            const int qpos0 = q0 + w * 16 + (lane >> 2);
            const int kbase = k0 + (lane & 3) * 2;
#pragma unroll
            for (int nf = 0; nf < 8; nf++) {
                const int kp = kbase + nf * 8;
                if (kp     > qpos0)     s_acc[nf][0] = NEG_INF;
                if (kp + 1 > qpos0)     s_acc[nf][1] = NEG_INF;
                if (kp     > qpos0 + 8) s_acc[nf][2] = NEG_INF;
                if (kp + 1 > qpos0 + 8) s_acc[nf][3] = NEG_INF;
            }
        }

#pragma unroll
        for (int half = 0; half < 2; half++) {
            float mx = NEG_INF;
#pragma unroll
            for (int nf = 0; nf < 8; nf++)
                mx = fmaxf(mx, fmaxf(s_acc[nf][half * 2], s_acc[nf][half * 2 + 1]));
            mx = fmaxf(mx, __shfl_xor_sync(0xffffffffu, mx, 1));
            mx = fmaxf(mx, __shfl_xor_sync(0xffffffffu, mx, 2));

            const float mnew  = fmaxf(m_run[half], mx);
            const float alpha = __expf(m_run[half] - mnew);
            m_run[half] = mnew;

            float sum = 0.0f;
#pragma unroll
            for (int nf = 0; nf < 8; nf++) {
                float p0 = __expf(s_acc[nf][half * 2]     - mnew);
                float p1 = __expf(s_acc[nf][half * 2 + 1] - mnew);
                s_acc[nf][half * 2]     = p0;
                s_acc[nf][half * 2 + 1] = p1;
                sum += p0 + p1;
            }
            sum += __shfl_xor_sync(0xffffffffu, sum, 1);
            sum += __shfl_xor_sync(0xffffffffu, sum, 2);
            l_run[half] = l_run[half] * alpha + sum;

#pragma unroll
            for (int dn = 0; dn < 8; dn++) {
                acc_o[dn][half * 2]     *= alpha;
                acc_o[dn][half * 2 + 1] *= alpha;
            }
        }

#pragma unroll
        for (int kc = 0; kc < 4; kc++) {
            uint32_t pah[4], pal[4];
#pragma unroll
            for (int q = 0; q < 2; q++) {
                const float* sc = s_acc[2 * kc + q];
                float h0 = bfhi(sc[0]), h1 = bfhi(sc[1]);
                float h2 = bfhi(sc[2]), h3 = bfhi(sc[3]);
                pah[q * 2 + 0] = bf2pack(h0, h1);
                pah[q * 2 + 1] = bf2pack(h2, h3);
                pal[q * 2 + 0] = bf2pack(sc[0] - h0, sc[1] - h1);
                pal[q * 2 + 1] = bf2pack(sc[2] - h2, sc[3] - h3);
            }
            uint32_t ah[4] = {pah[0], pah[1], pah[2], pah[3]};
            uint32_t al[4] = {pal[0], pal[1], pal[2], pal[3]};
#pragma unroll
            for (int dg = 0; dg < 4; dg++) {
                int r = v_r + kc * 16;
                int ch = v_c + dg * 2;
                uint32_t off = r * 128 + ((ch ^ (r & 7)) << 4);
                uint32_t vh[4], vl[4];
                ldsm_x4_t(vh, st + ATT_VH + off);
                ldsm_x4_t(vl, st + ATT_VL + off);
#pragma unroll
                for (int q = 0; q < 2; q++) {
                    float* o = acc_o[dg * 2 + q];
                    mma_bf16(o, ah, &vh[q * 2]);
                    mma_bf16(o, al, &vh[q * 2]);
                    mma_bf16(o, ah, &vl[q * 2]);
                }
            }
        }
        __syncthreads();
    }

    const float inv0 = 1.0f / l_run[0];
    const float inv1 = 1.0f / l_run[1];
    const int row0 = q0 + w * 16 + (lane >> 2);
    const size_t tok0 = (size_t)(b * SEQ + row0) * DIM + h * HDIM;
    const size_t tok1 = tok0 + 8 * DIM;
#pragma unroll
    for (int dn = 0; dn < 8; dn++) {
        const int d = dn * 8 + (lane & 3) * 2;
        float f0 = acc_o[dn][0] * inv0;
        float f1 = acc_o[dn][1] * inv0;
        float f2 = acc_o[dn][2] * inv1;
        float f3 = acc_o[dn][3] * inv1;
        unsigned short h0, l0, h1, l1, h2, l2, h3, l3;
        split1(f0, h0, l0); split1(f1, h1, l1);
        split1(f2, h2, l2); split1(f3, h3, l3);
        *(ushort2*)(g_o_hi + tok0 + d) = make_ushort2(h0, h1);
        *(ushort2*)(g_o_lo + tok0 + d) = make_ushort2(l0, l1);
        *(ushort2*)(g_o_hi + tok1 + d) = make_ushort2(h2, h3);
        *(ushort2*)(g_o_lo + tok1 + d) = make_ushort2(l2, l3);
    }
}

// ============================================================================
// launch
// ============================================================================
extern "C" void kernel_launch(void* const* d_in, const int* in_sizes, int n_in,
                              void* d_out, int out_size)
{
    const float* x  = (const float*)d_in[0];
    const float* Wq = (const float*)d_in[1];
    const float* Wk = (const float*)d_in[2];
    const float* Wv = (const float*)d_in[3];
    const float* Wo = (const float*)d_in[4];
    const float* bo = (const float*)d_in[5];
    float* out = (float*)d_out;

    cudaFuncSetAttribute(gemm_qkv_bf16,  cudaFuncAttributeMaxDynamicSharedMemorySize, GEMM_SMEM);
    cudaFuncSetAttribute(gemm_out_bf16,  cudaFuncAttributeMaxDynamicSharedMemorySize, GEMM_SMEM);
    cudaFuncSetAttribute(attn_mma_kernel, cudaFuncAttributeMaxDynamicSharedMemorySize, ATT_SMEM);

    // fused bf16 hi/lo splits (MLP=4 per thread)
    split_all_kernel<<<2048, 256>>>(x, Wq, Wk, Wv, Wo);

    // QKV projections -> head-major bf16 hi/lo (Q pre-scaled)
    dim3 gridQKV(DIM / 64, MTOT / 128, 3);
    gemm_qkv_bf16<<<gridQKV, 128, GEMM_SMEM>>>();

    // tensor-core flash attention (BQ=64, 2 CTAs/SM)
    dim3 gridAtt(SEQ / 64, NHEADS, BATCH);
    attn_mma_kernel<<<gridAtt, 128, ATT_SMEM>>>();

    // output projection + bias
    dim3 gridOut(DIM / 64, MTOT / 128);
    gemm_out_bf16<<<gridOut, 128, GEMM_SMEM>>>(bo, out);
}

// round 11
// speedup vs baseline: 1.0072x; 1.0072x over previous
#include <cuda_runtime.h>
#include <cuda_bf16.h>
#include <math.h>
#include <stdint.h>

#define DIM    1024
#define NHEADS 16
#define HDIM   64
#define BATCH  2
#define SEQ    2048
#define MTOT   (BATCH * SEQ)   // 4096

// ---------------- scratch (static device globals; no allocation) ----------------
__device__ unsigned short g_x_hi[MTOT * DIM];
__device__ unsigned short g_x_lo[MTOT * DIM];
__device__ unsigned short g_w_hi[4 * DIM * DIM];   // Wq, Wk, Wv, Wo
__device__ unsigned short g_w_lo[4 * DIM * DIM];
// Q/K/V head-major [B][H][T][D], bf16 hi/lo (Q pre-scaled by 1/8)
__device__ unsigned short g_q_hi[MTOT * DIM];
__device__ unsigned short g_q_lo[MTOT * DIM];
__device__ unsigned short g_k_hi[MTOT * DIM];
__device__ unsigned short g_k_lo[MTOT * DIM];
__device__ unsigned short g_v_hi[MTOT * DIM];
__device__ unsigned short g_v_lo[MTOT * DIM];
// attention output, token-major [MTOT][DIM], bf16 hi/lo
__device__ unsigned short g_o_hi[MTOT * DIM];
__device__ unsigned short g_o_lo[MTOT * DIM];

// ============================================================================
// helpers
// ============================================================================
__device__ __forceinline__ void split1(float v, unsigned short& h, unsigned short& l)
{
    __nv_bfloat16 hb = __float2bfloat16(v);
    h = __bfloat16_as_ushort(hb);
    l = __bfloat16_as_ushort(__float2bfloat16(v - __bfloat162float(hb)));
}
__device__ __forceinline__ void split4(const float4 v, ushort4& h, ushort4& l)
{
    split1(v.x, h.x, l.x);
    split1(v.y, h.y, l.y);
    split1(v.z, h.z, l.z);
    split1(v.w, h.w, l.w);
}
__device__ __forceinline__ uint32_t bf2pack(float a, float b)
{
    __nv_bfloat162 t = __floats2bfloat162_rn(a, b);
    return *reinterpret_cast<uint32_t*>(&t);
}
__device__ __forceinline__ float bfhi(float v)
{
    return __bfloat162float(__float2bfloat16(v));
}

// fused split, 4 independent float4s per thread (MLP=4).
__global__ void split_all_kernel(const float* __restrict__ x,
                                 const float* __restrict__ Wq,
                                 const float* __restrict__ Wk,
                                 const float* __restrict__ Wv,
                                 const float* __restrict__ Wo)
{
    const int blk = blockIdx.x;
    if (blk < 1024) {
        int base = blk * 1024 + threadIdx.x;
#pragma unroll
        for (int j = 0; j < 4; j++) {
            int i = base + j * 256;
            float4 v = ((const float4*)x)[i];
            ushort4 h, l;
            split4(v, h, l);
            ((ushort4*)g_x_hi)[i] = h;
            ((ushort4*)g_x_lo)[i] = l;
        }
    } else {
        int wbase = (blk - 1024) * 1024 + threadIdx.x;
#pragma unroll
        for (int j = 0; j < 4; j++) {
            int widx = wbase + j * 256;
            int z = widx >> 18;
            int i = widx & 262143;
            const float* w = (z == 0) ? Wq : (z == 1) ? Wk : (z == 2) ? Wv : Wo;
            float4 v = ((const float4*)w)[i];
            ushort4 h, l;
            split4(v, h, l);
            ((ushort4*)g_w_hi)[(size_t)z * 262144 + i] = h;
            ((ushort4*)g_w_lo)[(size_t)z * 262144 + i] = l;
        }
    }
}

// ============================================================================
// async / mma primitives
// ============================================================================
__device__ __forceinline__ void cp16(uint32_t dst, const void* src)
{
    asm volatile("cp.async.cg.shared.global [%0], [%1], 16;\n" :: "r"(dst), "l"(src));
}
__device__ __forceinline__ void cp_commit()
{
    asm volatile("cp.async.commit_group;\n");
}
template<int N> __device__ __forceinline__ void cp_wait()
{
    asm volatile("cp.async.wait_group %0;\n" :: "n"(N));
}
__device__ __forceinline__ void ldsm_x4(uint32_t* r, uint32_t addr)
{
    asm volatile("ldmatrix.sync.aligned.m8n8.x4.shared.b16 {%0,%1,%2,%3}, [%4];"
                 : "=r"(r[0]), "=r"(r[1]), "=r"(r[2]), "=r"(r[3]) : "r"(addr));
}
__device__ __forceinline__ void ldsm_x4_t(uint32_t* r, uint32_t addr)
{
    asm volatile("ldmatrix.sync.aligned.m8n8.x4.trans.shared.b16 {%0,%1,%2,%3}, [%4];"
                 : "=r"(r[0]), "=r"(r[1]), "=r"(r[2]), "=r"(r[3]) : "r"(addr));
}
__device__ __forceinline__ void mma_bf16(float* c, const uint32_t* a, const uint32_t* b)
{
    asm volatile("mma.sync.aligned.m16n8k16.row.col.f32.bf16.bf16.f32 "
                 "{%0,%1,%2,%3},{%4,%5,%6,%7},{%8,%9},{%0,%1,%2,%3};"
                 : "+f"(c[0]), "+f"(c[1]), "+f"(c[2]), "+f"(c[3])
                 : "r"(a[0]), "r"(a[1]), "r"(a[2]), "r"(a[3]), "r"(b[0]), "r"(b[1]));
}

// ============================================================================
// bf16x3 tensor-core GEMM:  C[M,N] = A[M,K] * B[N,K]^T  (exact R8 config)
// BM=128, BN=64, BK=64, 256 threads (8 warps: 4m x 2n), 2-stage cp.async,
// 2 CTAs/SM. 96 MMAs per warp between barriers.
// MODE 0: split + scatter into head-major bf16 hi/lo.  MODE 1: fp32 + bias.
// ============================================================================
#define STG_BYTES 49152
#define AH_OFF 0
#define AL_OFF 16384
#define BH_OFF 32768
#define BL_OFF 40960
#define GEMM_SMEM (2 * STG_BYTES)

template<int MODE>
__device__ __forceinline__ void gemm_bf16_body(
    const unsigned short* __restrict__ Ah, const unsigned short* __restrict__ Al,
    const unsigned short* __restrict__ Bh, const unsigned short* __restrict__ Bl,
    float scale,
    unsigned short* __restrict__ Chi, unsigned short* __restrict__ Clo,
    const float* __restrict__ bias, float* __restrict__ C)
{
    extern __shared__ char dsm[];
    const uint32_t sbase = (uint32_t)__cvta_generic_to_shared(dsm);

    const int tid  = threadIdx.x;
    const int bm   = blockIdx.y * 128;
    const int bn   = blockIdx.x * 64;
    const int lane = tid & 31;
    const int warp = tid >> 5;
    const int wm   = warp & 3;
    const int wn   = warp >> 2;

    auto load_stage = [&](int s, int k0) {
        const uint32_t sb = sbase + s * STG_BYTES;
#pragma unroll
        for (int t = 0; t < 4; t++) {
            int c   = tid + t * 256;
            int row = c >> 3, ch = c & 7;
            size_t   gofs = (size_t)(bm + row) * DIM + k0 + ch * 8;
            uint32_t sofs = row * 128 + ((ch ^ (row & 7)) << 4);
            cp16(sb + AH_OFF + sofs, Ah + gofs);
            cp16(sb + AL_OFF + sofs, Al + gofs);
        }
#pragma unroll
        for (int t = 0; t < 2; t++) {
            int c   = tid + t * 256;
            int row = c >> 3, ch = c & 7;
            size_t   gofs = (size_t)(bn + row) * DIM + k0 + ch * 8;
            uint32_t sofs = row * 128 + ((ch ^ (row & 7)) << 4);
            cp16(sb + BH_OFF + sofs, Bh + gofs);
            cp16(sb + BL_OFF + sofs, Bl + gofs);
        }
    };

    float acc[2][4][4];
#pragma unroll
    for (int i = 0; i < 2; i++)
#pragma unroll
        for (int j = 0; j < 4; j++)
#pragma unroll
            for (int k = 0; k < 4; k++) acc[i][j][k] = 0.0f;

    const int a_r = wm * 32 + (lane & 15);
    const int a_k = (lane >> 4);
    const int a_x = a_r & 7;
    const int b_r = wn * 32 + (lane & 7) + ((lane >> 4) << 3);
    const int b_k = (lane >> 3) & 1;
    const int b_x = b_r & 7;

    load_stage(0, 0);
    cp_commit();

    constexpr int NIT = DIM / 64;   // 16
    for (int it = 0; it < NIT; ++it) {
        const int s = it & 1;
        if (it + 1 < NIT) {
            load_stage(s ^ 1, (it + 1) * 64);
            cp_commit();
            cp_wait<1>();
        } else {
            cp_wait<0>();
        }
        __syncthreads();

        const uint32_t sb = sbase + s * STG_BYTES;
#pragma unroll
        for (int ks = 0; ks < 4; ks++) {
            uint32_t ah[2][4], al[2][4], bh[2][4], bl[2][4];
#pragma unroll
            for (int mf = 0; mf < 2; mf++) {
                uint32_t off = (a_r + mf * 16) * 128 + ((((ks << 1) | a_k) ^ a_x) << 4);
                ldsm_x4(ah[mf], sb + AH_OFF + off);
                ldsm_x4(al[mf], sb + AL_OFF + off);
            }
#pragma unroll
            for (int nf2 = 0; nf2 < 2; nf2++) {
                uint32_t off = (b_r + nf2 * 16) * 128 + ((((ks << 1) | b_k) ^ b_x) << 4);
                ldsm_x4(bh[nf2], sb + BH_OFF + off);
                ldsm_x4(bl[nf2], sb + BL_OFF + off);
            }
#pragma unroll
            for (int mf = 0; mf < 2; mf++)
#pragma unroll
                for (int nf = 0; nf < 4; nf++) {
                    const uint32_t* bhp = &bh[nf >> 1][(nf & 1) * 2];
                    const uint32_t* blp = &bl[nf >> 1][(nf & 1) * 2];
                    mma_bf16(acc[mf][nf], ah[mf], bhp);
                    mma_bf16(acc[mf][nf], al[mf], bhp);
                    mma_bf16(acc[mf][nf], ah[mf], blp);
                }
        }
        __syncthreads();
    }

    // epilogue
#pragma unroll
    for (int mf = 0; mf < 2; mf++) {
        const int row0 = bm + wm * 32 + mf * 16 + (lane >> 2);
#pragma unroll
        for (int nf = 0; nf < 4; nf++) {
            const int col = bn + wn * 32 + nf * 8 + (lane & 3) * 2;
            if (MODE == 0) {
                const int h = col >> 6, d = col & 63;
#pragma unroll
                for (int half = 0; half < 2; half++) {
                    const int row = row0 + half * 8;
                    const int b = row >> 11, t = row & 2047;
                    const size_t dst = (((size_t)(b * NHEADS + h) * SEQ) + t) * HDIM + d;
                    float f0 = acc[mf][nf][half * 2 + 0] * scale;
                    float f1 = acc[mf][nf][half * 2 + 1] * scale;
                    unsigned short h0, l0, h1, l1;
                    split1(f0, h0, l0);
                    split1(f1, h1, l1);
                    *(ushort2*)(Chi + dst) = make_ushort2(h0, h1);
                    *(ushort2*)(Clo + dst) = make_ushort2(l0, l1);
                }
            } else {
                float b0 = bias[col], b1 = bias[col + 1];
                float2 v0 = make_float2(acc[mf][nf][0] + b0, acc[mf][nf][1] + b1);
                float2 v1 = make_float2(acc[mf][nf][2] + b0, acc[mf][nf][3] + b1);
                *(float2*)(C + (size_t)row0 * DIM + col)       = v0;
                *(float2*)(C + (size_t)(row0 + 8) * DIM + col) = v1;
            }
        }
    }
}

__global__ void __launch_bounds__(256, 2) gemm_qkv_bf16()
{
    const int z = blockIdx.z;
    unsigned short* Chi = (z == 0) ? g_q_hi : (z == 1) ? g_k_hi : g_v_hi;
    unsigned short* Clo = (z == 0) ? g_q_lo : (z == 1) ? g_k_lo : g_v_lo;
    const float scale = (z == 0) ? 0.125f : 1.0f;
    gemm_bf16_body<0>(g_x_hi, g_x_lo,
                      g_w_hi + (size_t)z * DIM * DIM, g_w_lo + (size_t)z * DIM * DIM,
                      scale, Chi, Clo, nullptr, nullptr);
}

__global__ void __launch_bounds__(256, 2) gemm_out_bf16(
    const float* __restrict__ bo, float* __restrict__ out)
{
    gemm_bf16_body<1>(g_o_hi, g_o_lo,
                      g_w_hi + (size_t)3 * DIM * DIM, g_w_lo + (size_t)3 * DIM * DIM,
                      1.0f, nullptr, nullptr, bo, out);
}

// ============================================================================
// Tensor-core flash attention (bf16x3, causal).
// BQ=64: 128 threads (4 warps x 16 q-rows), BK=64, 3-stage KV ring.
// smem 112KB -> 2 CTAs/SM. Math identical to R8.
// ============================================================================
#define ATT_QH 0
#define ATT_QL 8192
#define ATT_STG0 16384
#define ATT_STG_BYTES 32768       // KH 8K | KL 8K | VH 8K | VL 8K
#define ATT_KH 0
#define ATT_KL 8192
#define ATT_VH 16384
#define ATT_VL 24576
#define ATT_NSTG 3
#define ATT_SMEM (ATT_STG0 + ATT_NSTG * ATT_STG_BYTES)   // 114688 = 112KB

#define NEG_INF __int_as_float(0xff800000)

__global__ void __launch_bounds__(128, 1) attn_mma_kernel()
{
    extern __shared__ char dsm[];
    const uint32_t sbase = (uint32_t)__cvta_generic_to_shared(dsm);

    const int tid  = threadIdx.x;
    const int lane = tid & 31;
    const int w    = tid >> 5;           // 0..3
    const int qb   = (gridDim.x - 1) - blockIdx.x;   // big tiles first
    const int h    = blockIdx.y;
    const int b    = blockIdx.z;
    const int q0   = qb * 64;

    const size_t head = (size_t)(b * NHEADS + h) * SEQ * HDIM;
    const unsigned short* Qh = g_q_hi + head;
    const unsigned short* Ql = g_q_lo + head;
    const unsigned short* Kh = g_k_hi + head;
    const unsigned short* Kl = g_k_lo + head;
    const unsigned short* Vh = g_v_hi + head;
    const unsigned short* Vl = g_v_lo + head;

    // ---- load Q tile (64 rows x 64 bf16, hi+lo) ----
#pragma unroll
    for (int t = 0; t < 4; t++) {
        int c = tid + t * 128;           // 0..511
        int row = c >> 3, ch = c & 7;
        size_t   g = (size_t)(q0 + row) * HDIM + ch * 8;
        uint32_t sofs = row * 128 + ((ch ^ (row & 7)) << 4);
        cp16(sbase + ATT_QH + sofs, Qh + g);
        cp16(sbase + ATT_QL + sofs, Ql + g);
    }

    auto load_kv = [&](int s, int k0) {
        const uint32_t st = sbase + ATT_STG0 + s * ATT_STG_BYTES;
#pragma unroll
        for (int t = 0; t < 4; t++) {
            int c = tid + t * 128;       // 0..511
            int row = c >> 3, ch = c & 7;
            size_t   g = (size_t)(k0 + row) * HDIM + ch * 8;
            uint32_t sofs = row * 128 + ((ch ^ (row & 7)) << 4);
            cp16(st + ATT_KH + sofs, Kh + g);
            cp16(st + ATT_KL + sofs, Kl + g);
            cp16(st + ATT_VH + sofs, Vh + g);
            cp16(st + ATT_VL + sofs, Vl + g);
        }
    };

    const int kmax = qb;

    // prologue: Q + stage0 in group 0; stage1 in group 1
    load_kv(0, 0);
    cp_commit();
    if (kmax >= 1) {
        load_kv(1, 64);
        cp_commit();
    }

    const int a_r = w * 16 + (lane & 15);
    const int a_k = lane >> 4;
    const int a_x = a_r & 7;
    const int k_r = (lane & 7) + ((lane >> 4) << 3);
    const int k_k = (lane >> 3) & 1;
    const int v_r = (lane & 7) + (((lane >> 3) & 1) << 3);
    const int v_c = lane >> 4;

    uint32_t qh[4][4], ql[4][4];

    float m_run[2] = {NEG_INF, NEG_INF};
    float l_run[2] = {0.0f, 0.0f};
    float acc_o[8][4];
#pragma unroll
    for (int i = 0; i < 8; i++)
#pragma unroll
        for (int j = 0; j < 4; j++) acc_o[i][j] = 0.0f;

    int s = 0;   // stage of current kb
    for (int kb = 0; kb <= kmax; kb++) {
        const int k0 = kb * 64;
        if (kb + 2 <= kmax) {
            load_kv((s + 2) % ATT_NSTG, (kb + 2) * 64);
            cp_commit();
            cp_wait<2>();
        } else if (kb + 1 <= kmax) {
            cp_wait<1>();
        } else {
            cp_wait<0>();
        }
        __syncthreads();

        if (kb == 0) {
            // Q fragments -> registers (once)
#pragma unroll
            for (int ks = 0; ks < 4; ks++) {
                uint32_t off = a_r * 128 + ((((ks << 1) | a_k) ^ a_x) << 4);
                ldsm_x4(qh[ks], sbase + ATT_QH + off);
                ldsm_x4(ql[ks], sbase + ATT_QL + off);
            }
        }

        const uint32_t st = sbase + ATT_STG0 + s * ATT_STG_BYTES;

        // ---- S = Q K^T (16 x 64 per warp) ----
        float s_acc[8][4];
#pragma unroll
        for (int i = 0; i < 8; i++)
#pragma unroll
            for (int j = 0; j < 4; j++) s_acc[i][j] = 0.0f;

#pragma unroll
        for (int ks = 0; ks < 4; ks++) {
            uint32_t bh[4][4], bl[4][4];
#pragma unroll
            for (int nf2 = 0; nf2 < 4; nf2++) {
                int r = k_r + nf2 * 16;
                uint32_t off = r * 128 + ((((ks << 1) | k_k) ^ (r & 7)) << 4);
                ldsm_x4(bh[nf2], st + ATT_KH + off);
                ldsm_x4(bl[nf2], st + ATT_KL + off);
            }
#pragma unroll
            for (int nf = 0; nf < 8; nf++) {
                const uint32_t* bhp = &bh[nf >> 1][(nf & 1) * 2];
                const uint32_t* blp = &bl[nf >> 1][(nf & 1) * 2];
                mma_bf16(s_acc[nf], qh[ks], bhp);
                mma_bf16(s_acc[nf], ql[ks], bhp);
                mma_bf16(s_acc[nf], qh[ks], blp);
            }
        }

        // ---- causal mask (diagonal tile only) ----
        if (kb == qb) {
            const int qpos0 = q0 + w * 16 + (lane >> 2);
            const int kbase = k0 + (lane & 3) * 2;
#pragma unroll
            for (int nf = 0; nf < 8; nf++) {
                const int kp = kbase + nf * 8;
                if (kp     > qpos0)     s_acc[nf][0] = NEG_INF;
                if (kp + 1 > qpos0)     s_acc[nf][1] = NEG_INF;
                if (kp     > qpos0 + 8) s_acc[nf][2] = NEG_INF;
                if (kp + 1 > qpos0 + 8) s_acc[nf][3] = NEG_INF;
            }
        }

        // ---- online softmax (register-level, quad reduce) ----
#pragma unroll
        for (int half = 0; half < 2; half++) {
            float mx = NEG_INF;
#pragma unroll
            for (int nf = 0; nf < 8; nf++)
                mx = fmaxf(mx, fmaxf(s_acc[nf][half * 2], s_acc[nf][half * 2 + 1]));
            mx = fmaxf(mx, __shfl_xor_sync(0xffffffffu, mx, 1));
            mx = fmaxf(mx, __shfl_xor_sync(0xffffffffu, mx, 2));

            const float mnew  = fmaxf(m_run[half], mx);
            const float alpha = __expf(m_run[half] - mnew);
            m_run[half] = mnew;

            float sum = 0.0f;
#pragma unroll
            for (int nf = 0; nf < 8; nf++) {
                float p0 = __expf(s_acc[nf][half * 2]     - mnew);
                float p1 = __expf(s_acc[nf][half * 2 + 1] - mnew);
                s_acc[nf][half * 2]     = p0;
                s_acc[nf][half * 2 + 1] = p1;
                sum += p0 + p1;
            }
            sum += __shfl_xor_sync(0xffffffffu, sum, 1);
            sum += __shfl_xor_sync(0xffffffffu, sum, 2);
            l_run[half] = l_run[half] * alpha + sum;

#pragma unroll
            for (int dn = 0; dn < 8; dn++) {
                acc_o[dn][half * 2]     *= alpha;
                acc_o[dn][half * 2 + 1] *= alpha;
            }
        }

        // ---- O += P V ----
#pragma unroll
        for (int kc = 0; kc < 4; kc++) {
            uint32_t pah[4], pal[4];
#pragma unroll
            for (int q = 0; q < 2; q++) {
                const float* sc = s_acc[2 * kc + q];
                float h0 = bfhi(sc[0]), h1 = bfhi(sc[1]);
                float h2 = bfhi(sc[2]), h3 = bfhi(sc[3]);
                pah[q * 2 + 0] = bf2pack(h0, h1);
                pah[q * 2 + 1] = bf2pack(h2, h3);
                pal[q * 2 + 0] = bf2pack(sc[0] - h0, sc[1] - h1);
                pal[q * 2 + 1] = bf2pack(sc[2] - h2, sc[3] - h3);
            }
            uint32_t ah[4] = {pah[0], pah[1], pah[2], pah[3]};
            uint32_t al[4] = {pal[0], pal[1], pal[2], pal[3]};
#pragma unroll
            for (int dg = 0; dg < 4; dg++) {
                int r = v_r + kc * 16;
                int ch = v_c + dg * 2;
                uint32_t off = r * 128 + ((ch ^ (r & 7)) << 4);
                uint32_t vh[4], vl[4];
                ldsm_x4_t(vh, st + ATT_VH + off);
                ldsm_x4_t(vl, st + ATT_VL + off);
#pragma unroll
                for (int q = 0; q < 2; q++) {
                    float* o = acc_o[dg * 2 + q];
                    mma_bf16(o, ah, &vh[q * 2]);
                    mma_bf16(o, al, &vh[q * 2]);
                    mma_bf16(o, ah, &vl[q * 2]);
                }
            }
        }
        __syncthreads();
        s = (s + 1) % ATT_NSTG;
    }

    // ---- epilogue: normalize, split, store token-major [MTOT][DIM] ----
    const float inv0 = 1.0f / l_run[0];
    const float inv1 = 1.0f / l_run[1];
    const int row0 = q0 + w * 16 + (lane >> 2);
    const size_t tok0 = (size_t)(b * SEQ + row0) * DIM + h * HDIM;
    const size_t tok1 = tok0 + 8 * DIM;
#pragma unroll
    for (int dn = 0; dn < 8; dn++) {
        const int d = dn * 8 + (lane & 3) * 2;
        float f0 = acc_o[dn][0] * inv0;
        float f1 = acc_o[dn][1] * inv0;
        float f2 = acc_o[dn][2] * inv1;
        float f3 = acc_o[dn][3] * inv1;
        unsigned short h0, l0, h1, l1, h2, l2, h3, l3;
        split1(f0, h0, l0); split1(f1, h1, l1);
        split1(f2, h2, l2); split1(f3, h3, l3);
        *(ushort2*)(g_o_hi + tok0 + d) = make_ushort2(h0, h1);
        *(ushort2*)(g_o_lo + tok0 + d) = make_ushort2(l0, l1);
        *(ushort2*)(g_o_hi + tok1 + d) = make_ushort2(h2, h3);
        *(ushort2*)(g_o_lo + tok1 + d) = make_ushort2(l2, l3);
    }
}

// ============================================================================
// launch
// ============================================================================
extern "C" void kernel_launch(void* const* d_in, const int* in_sizes, int n_in,
                              void* d_out, int out_size)
{
    const float* x  = (const float*)d_in[0];
    const float* Wq = (const float*)d_in[1];
    const float* Wk = (const float*)d_in[2];
    const float* Wv = (const float*)d_in[3];
    const float* Wo = (const float*)d_in[4];
    const float* bo = (const float*)d_in[5];
    float* out = (float*)d_out;

    cudaFuncSetAttribute(gemm_qkv_bf16,  cudaFuncAttributeMaxDynamicSharedMemorySize, GEMM_SMEM);
    cudaFuncSetAttribute(gemm_out_bf16,  cudaFuncAttributeMaxDynamicSharedMemorySize, GEMM_SMEM);
    cudaFuncSetAttribute(attn_mma_kernel, cudaFuncAttributeMaxDynamicSharedMemorySize, ATT_SMEM);

    // fused bf16 hi/lo splits (MLP=4 per thread)
    split_all_kernel<<<2048, 256>>>(x, Wq, Wk, Wv, Wo);

    // QKV projections -> head-major bf16 hi/lo (Q pre-scaled)
    dim3 gridQKV(DIM / 64, MTOT / 128, 3);
    gemm_qkv_bf16<<<gridQKV, 256, GEMM_SMEM>>>();

    // tensor-core flash attention (BQ=64, 3-stage KV ring, 2 CTAs/SM)
    dim3 gridAtt(SEQ / 64, NHEADS, BATCH);
    attn_mma_kernel<<<gridAtt, 128, ATT_SMEM>>>();

    // output projection + bias
    dim3 gridOut(DIM / 64, MTOT / 128);
    gemm_out_bf16<<<gridOut, 256, GEMM_SMEM>>>(bo, out);
}

// round 12
// speedup vs baseline: 1.0096x; 1.0024x over previous
#include <cuda_runtime.h>
#include <cuda_bf16.h>
#include <math.h>
#include <stdint.h>

#define DIM    1024
#define NHEADS 16
#define HDIM   64
#define BATCH  2
#define SEQ    2048
#define MTOT   (BATCH * SEQ)   // 4096

// ---------------- scratch (static device globals; no allocation) ----------------
__device__ unsigned short g_x_hi[MTOT * DIM];
__device__ unsigned short g_x_lo[MTOT * DIM];
__device__ unsigned short g_w_hi[4 * DIM * DIM];   // Wq, Wk, Wv, Wo
__device__ unsigned short g_w_lo[4 * DIM * DIM];
// Q/K/V head-major [B][H][T][D], bf16 hi/lo (Q pre-scaled by 1/8)
__device__ unsigned short g_q_hi[MTOT * DIM];
__device__ unsigned short g_q_lo[MTOT * DIM];
__device__ unsigned short g_k_hi[MTOT * DIM];
__device__ unsigned short g_k_lo[MTOT * DIM];
__device__ unsigned short g_v_hi[MTOT * DIM];
__device__ unsigned short g_v_lo[MTOT * DIM];
// attention output, token-major [MTOT][DIM], bf16 hi/lo
__device__ unsigned short g_o_hi[MTOT * DIM];
__device__ unsigned short g_o_lo[MTOT * DIM];

// ============================================================================
// helpers
// ============================================================================
__device__ __forceinline__ void split1(float v, unsigned short& h, unsigned short& l)
{
    __nv_bfloat16 hb = __float2bfloat16(v);
    h = __bfloat16_as_ushort(hb);
    l = __bfloat16_as_ushort(__float2bfloat16(v - __bfloat162float(hb)));
}
__device__ __forceinline__ void split4(const float4 v, ushort4& h, ushort4& l)
{
    split1(v.x, h.x, l.x);
    split1(v.y, h.y, l.y);
    split1(v.z, h.z, l.z);
    split1(v.w, h.w, l.w);
}
__device__ __forceinline__ uint32_t bf2pack(float a, float b)
{
    __nv_bfloat162 t = __floats2bfloat162_rn(a, b);
    return *reinterpret_cast<uint32_t*>(&t);
}
__device__ __forceinline__ float bfhi(float v)
{
    return __bfloat162float(__float2bfloat16(v));
}

// fused split, 4 independent float4s per thread (MLP=4).
__global__ void split_all_kernel(const float* __restrict__ x,
                                 const float* __restrict__ Wq,
                                 const float* __restrict__ Wk,
                                 const float* __restrict__ Wv,
                                 const float* __restrict__ Wo)
{
    const int blk = blockIdx.x;
    if (blk < 1024) {
        int base = blk * 1024 + threadIdx.x;
#pragma unroll
        for (int j = 0; j < 4; j++) {
            int i = base + j * 256;
            float4 v = ((const float4*)x)[i];
            ushort4 h, l;
            split4(v, h, l);
            ((ushort4*)g_x_hi)[i] = h;
            ((ushort4*)g_x_lo)[i] = l;
        }
    } else {
        int wbase = (blk - 1024) * 1024 + threadIdx.x;
#pragma unroll
        for (int j = 0; j < 4; j++) {
            int widx = wbase + j * 256;
            int z = widx >> 18;
            int i = widx & 262143;
            const float* w = (z == 0) ? Wq : (z == 1) ? Wk : (z == 2) ? Wv : Wo;
            float4 v = ((const float4*)w)[i];
            ushort4 h, l;
            split4(v, h, l);
            ((ushort4*)g_w_hi)[(size_t)z * 262144 + i] = h;
            ((ushort4*)g_w_lo)[(size_t)z * 262144 + i] = l;
        }
    }
}

// ============================================================================
// async / mma primitives
// ============================================================================
__device__ __forceinline__ void cp16(uint32_t dst, const void* src)
{
    asm volatile("cp.async.cg.shared.global [%0], [%1], 16;\n" :: "r"(dst), "l"(src));
}
__device__ __forceinline__ void cp_commit()
{
    asm volatile("cp.async.commit_group;\n");
}
template<int N> __device__ __forceinline__ void cp_wait()
{
    asm volatile("cp.async.wait_group %0;\n" :: "n"(N));
}
__device__ __forceinline__ void ldsm_x4(uint32_t* r, uint32_t addr)
{
    asm volatile("ldmatrix.sync.aligned.m8n8.x4.shared.b16 {%0,%1,%2,%3}, [%4];"
                 : "=r"(r[0]), "=r"(r[1]), "=r"(r[2]), "=r"(r[3]) : "r"(addr));
}
__device__ __forceinline__ void ldsm_x4_t(uint32_t* r, uint32_t addr)
{
    asm volatile("ldmatrix.sync.aligned.m8n8.x4.trans.shared.b16 {%0,%1,%2,%3}, [%4];"
                 : "=r"(r[0]), "=r"(r[1]), "=r"(r[2]), "=r"(r[3]) : "r"(addr));
}
__device__ __forceinline__ void mma_bf16(float* c, const uint32_t* a, const uint32_t* b)
{
    asm volatile("mma.sync.aligned.m16n8k16.row.col.f32.bf16.bf16.f32 "
                 "{%0,%1,%2,%3},{%4,%5,%6,%7},{%8,%9},{%0,%1,%2,%3};"
                 : "+f"(c[0]), "+f"(c[1]), "+f"(c[2]), "+f"(c[3])
                 : "r"(a[0]), "r"(a[1]), "r"(a[2]), "r"(a[3]), "r"(b[0]), "r"(b[1]));
}

// ============================================================================
// bf16x3 tensor-core GEMM:  C[M,N] = A[M,K] * B[N,K]^T
// BM=128, BN=64, BK=64, 256 threads (8 warps: 4m x 2n), 2-stage cp.async,
// 2 CTAs/SM. Ootomo terms issued in 3 PASSES over 8 independent accumulators
// (breaks the per-accumulator RAW chain of back-to-back HMMAs).
// Per-accumulator term order unchanged (hh, lh, hl) -> bit-identical result.
// MODE 0: split + scatter into head-major bf16 hi/lo.  MODE 1: fp32 + bias.
// ============================================================================
#define STG_BYTES 49152
#define AH_OFF 0
#define AL_OFF 16384
#define BH_OFF 32768
#define BL_OFF 40960
#define GEMM_SMEM (2 * STG_BYTES)

template<int MODE>
__device__ __forceinline__ void gemm_bf16_body(
    const unsigned short* __restrict__ Ah, const unsigned short* __restrict__ Al,
    const unsigned short* __restrict__ Bh, const unsigned short* __restrict__ Bl,
    float scale,
    unsigned short* __restrict__ Chi, unsigned short* __restrict__ Clo,
    const float* __restrict__ bias, float* __restrict__ C)
{
    extern __shared__ char dsm[];
    const uint32_t sbase = (uint32_t)__cvta_generic_to_shared(dsm);

    const int tid  = threadIdx.x;
    const int bm   = blockIdx.y * 128;
    const int bn   = blockIdx.x * 64;
    const int lane = tid & 31;
    const int warp = tid >> 5;
    const int wm   = warp & 3;
    const int wn   = warp >> 2;

    auto load_stage = [&](int s, int k0) {
        const uint32_t sb = sbase + s * STG_BYTES;
#pragma unroll
        for (int t = 0; t < 4; t++) {
            int c   = tid + t * 256;
            int row = c >> 3, ch = c & 7;
            size_t   gofs = (size_t)(bm + row) * DIM + k0 + ch * 8;
            uint32_t sofs = row * 128 + ((ch ^ (row & 7)) << 4);
            cp16(sb + AH_OFF + sofs, Ah + gofs);
            cp16(sb + AL_OFF + sofs, Al + gofs);
        }
#pragma unroll
        for (int t = 0; t < 2; t++) {
            int c   = tid + t * 256;
            int row = c >> 3, ch = c & 7;
            size_t   gofs = (size_t)(bn + row) * DIM + k0 + ch * 8;
            uint32_t sofs = row * 128 + ((ch ^ (row & 7)) << 4);
            cp16(sb + BH_OFF + sofs, Bh + gofs);
            cp16(sb + BL_OFF + sofs, Bl + gofs);
        }
    };

    float acc[2][4][4];
#pragma unroll
    for (int i = 0; i < 2; i++)
#pragma unroll
        for (int j = 0; j < 4; j++)
#pragma unroll
            for (int k = 0; k < 4; k++) acc[i][j][k] = 0.0f;

    const int a_r = wm * 32 + (lane & 15);
    const int a_k = (lane >> 4);
    const int a_x = a_r & 7;
    const int b_r = wn * 32 + (lane & 7) + ((lane >> 4) << 3);
    const int b_k = (lane >> 3) & 1;
    const int b_x = b_r & 7;

    load_stage(0, 0);
    cp_commit();

    constexpr int NIT = DIM / 64;   // 16
    for (int it = 0; it < NIT; ++it) {
        const int s = it & 1;
        if (it + 1 < NIT) {
            load_stage(s ^ 1, (it + 1) * 64);
            cp_commit();
            cp_wait<1>();
        } else {
            cp_wait<0>();
        }
        __syncthreads();

        const uint32_t sb = sbase + s * STG_BYTES;
#pragma unroll
        for (int ks = 0; ks < 4; ks++) {
            uint32_t ah[2][4], al[2][4], bh[2][4], bl[2][4];
#pragma unroll
            for (int mf = 0; mf < 2; mf++) {
                uint32_t off = (a_r + mf * 16) * 128 + ((((ks << 1) | a_k) ^ a_x) << 4);
                ldsm_x4(ah[mf], sb + AH_OFF + off);
                ldsm_x4(al[mf], sb + AL_OFF + off);
            }
#pragma unroll
            for (int nf2 = 0; nf2 < 2; nf2++) {
                uint32_t off = (b_r + nf2 * 16) * 128 + ((((ks << 1) | b_k) ^ b_x) << 4);
                ldsm_x4(bh[nf2], sb + BH_OFF + off);
                ldsm_x4(bl[nf2], sb + BL_OFF + off);
            }
            // pass 1: hi*hi over all 8 independent accumulators
#pragma unroll
            for (int mf = 0; mf < 2; mf++)
#pragma unroll
                for (int nf = 0; nf < 4; nf++)
                    mma_bf16(acc[mf][nf], ah[mf], &bh[nf >> 1][(nf & 1) * 2]);
            // pass 2: lo*hi
#pragma unroll
            for (int mf = 0; mf < 2; mf++)
#pragma unroll
                for (int nf = 0; nf < 4; nf++)
                    mma_bf16(acc[mf][nf], al[mf], &bh[nf >> 1][(nf & 1) * 2]);
            // pass 3: hi*lo
#pragma unroll
            for (int mf = 0; mf < 2; mf++)
#pragma unroll
                for (int nf = 0; nf < 4; nf++)
                    mma_bf16(acc[mf][nf], ah[mf], &bl[nf >> 1][(nf & 1) * 2]);
        }
        __syncthreads();
    }

    // epilogue
#pragma unroll
    for (int mf = 0; mf < 2; mf++) {
        const int row0 = bm + wm * 32 + mf * 16 + (lane >> 2);
#pragma unroll
        for (int nf = 0; nf < 4; nf++) {
            const int col = bn + wn * 32 + nf * 8 + (lane & 3) * 2;
            if (MODE == 0) {
                const int h = col >> 6, d = col & 63;
#pragma unroll
                for (int half = 0; half < 2; half++) {
                    const int row = row0 + half * 8;
                    const int b = row >> 11, t = row & 2047;
                    const size_t dst = (((size_t)(b * NHEADS + h) * SEQ) + t) * HDIM + d;
                    float f0 = acc[mf][nf][half * 2 + 0] * scale;
                    float f1 = acc[mf][nf][half * 2 + 1] * scale;
                    unsigned short h0, l0, h1, l1;
                    split1(f0, h0, l0);
                    split1(f1, h1, l1);
                    *(ushort2*)(Chi + dst) = make_ushort2(h0, h1);
                    *(ushort2*)(Clo + dst) = make_ushort2(l0, l1);
                }
            } else {
                float b0 = bias[col], b1 = bias[col + 1];
                float2 v0 = make_float2(acc[mf][nf][0] + b0, acc[mf][nf][1] + b1);
                float2 v1 = make_float2(acc[mf][nf][2] + b0, acc[mf][nf][3] + b1);
                *(float2*)(C + (size_t)row0 * DIM + col)       = v0;
                *(float2*)(C + (size_t)(row0 + 8) * DIM + col) = v1;
            }
        }
    }
}

__global__ void __launch_bounds__(256, 2) gemm_qkv_bf16()
{
    const int z = blockIdx.z;
    unsigned short* Chi = (z == 0) ? g_q_hi : (z == 1) ? g_k_hi : g_v_hi;
    unsigned short* Clo = (z == 0) ? g_q_lo : (z == 1) ? g_k_lo : g_v_lo;
    const float scale = (z == 0) ? 0.125f : 1.0f;
    gemm_bf16_body<0>(g_x_hi, g_x_lo,
                      g_w_hi + (size_t)z * DIM * DIM, g_w_lo + (size_t)z * DIM * DIM,
                      scale, Chi, Clo, nullptr, nullptr);
}

__global__ void __launch_bounds__(256, 2) gemm_out_bf16(
    const float* __restrict__ bo, float* __restrict__ out)
{
    gemm_bf16_body<1>(g_o_hi, g_o_lo,
                      g_w_hi + (size_t)3 * DIM * DIM, g_w_lo + (size_t)3 * DIM * DIM,
                      1.0f, nullptr, nullptr, bo, out);
}

// ============================================================================
// Tensor-core flash attention (bf16x3, causal).
// BQ=64: 128 threads (4 warps x 16 q-rows), BK=64, 3-stage KV ring, 2 CTAs/SM.
// MMA terms issued in passes over independent accumulators (see GEMM note).
// ============================================================================
#define ATT_QH 0
#define ATT_QL 8192
#define ATT_STG0 16384
#define ATT_STG_BYTES 32768       // KH 8K | KL 8K | VH 8K | VL 8K
#define ATT_KH 0
#define ATT_KL 8192
#define ATT_VH 16384
#define ATT_VL 24576
#define ATT_NSTG 3
#define ATT_SMEM (ATT_STG0 + ATT_NSTG * ATT_STG_BYTES)   // 114688 = 112KB

#define NEG_INF __int_as_float(0xff800000)

__global__ void __launch_bounds__(128, 1) attn_mma_kernel()
{
    extern __shared__ char dsm[];
    const uint32_t sbase = (uint32_t)__cvta_generic_to_shared(dsm);

    const int tid  = threadIdx.x;
    const int lane = tid & 31;
    const int w    = tid >> 5;           // 0..3
    const int qb   = (gridDim.x - 1) - blockIdx.x;   // big tiles first
    const int h    = blockIdx.y;
    const int b    = blockIdx.z;
    const int q0   = qb * 64;

    const size_t head = (size_t)(b * NHEADS + h) * SEQ * HDIM;
    const unsigned short* Qh = g_q_hi + head;
    const unsigned short* Ql = g_q_lo + head;
    const unsigned short* Kh = g_k_hi + head;
    const unsigned short* Kl = g_k_lo + head;
    const unsigned short* Vh = g_v_hi + head;
    const unsigned short* Vl = g_v_lo + head;

    // ---- load Q tile (64 rows x 64 bf16, hi+lo) ----
#pragma unroll
    for (int t = 0; t < 4; t++) {
        int c = tid + t * 128;           // 0..511
        int row = c >> 3, ch = c & 7;
        size_t   g = (size_t)(q0 + row) * HDIM + ch * 8;
        uint32_t sofs = row * 128 + ((ch ^ (row & 7)) << 4);
        cp16(sbase + ATT_QH + sofs, Qh + g);
        cp16(sbase + ATT_QL + sofs, Ql + g);
    }

    auto load_kv = [&](int s, int k0) {
        const uint32_t st = sbase + ATT_STG0 + s * ATT_STG_BYTES;
#pragma unroll
        for (int t = 0; t < 4; t++) {
            int c = tid + t * 128;       // 0..511
            int row = c >> 3, ch = c & 7;
            size_t   g = (size_t)(k0 + row) * HDIM + ch * 8;
            uint32_t sofs = row * 128 + ((ch ^ (row & 7)) << 4);
            cp16(st + ATT_KH + sofs, Kh + g);
            cp16(st + ATT_KL + sofs, Kl + g);
            cp16(st + ATT_VH + sofs, Vh + g);
            cp16(st + ATT_VL + sofs, Vl + g);
        }
    };

    const int kmax = qb;

    load_kv(0, 0);
    cp_commit();
    if (kmax >= 1) {
        load_kv(1, 64);
        cp_commit();
    }

    const int a_r = w * 16 + (lane & 15);
    const int a_k = lane >> 4;
    const int a_x = a_r & 7;
    const int k_r = (lane & 7) + ((lane >> 4) << 3);
    const int k_k = (lane >> 3) & 1;
    const int v_r = (lane & 7) + (((lane >> 3) & 1) << 3);
    const int v_c = lane >> 4;

    uint32_t qh[4][4], ql[4][4];

    float m_run[2] = {NEG_INF, NEG_INF};
    float l_run[2] = {0.0f, 0.0f};
    float acc_o[8][4];
#pragma unroll
    for (int i = 0; i < 8; i++)
#pragma unroll
        for (int j = 0; j < 4; j++) acc_o[i][j] = 0.0f;

    int s = 0;
    for (int kb = 0; kb <= kmax; kb++) {
        const int k0 = kb * 64;
        if (kb + 2 <= kmax) {
            load_kv((s + 2) % ATT_NSTG, (kb + 2) * 64);
            cp_commit();
            cp_wait<2>();
        } else if (kb + 1 <= kmax) {
            cp_wait<1>();
        } else {
            cp_wait<0>();
        }
        __syncthreads();

        if (kb == 0) {
#pragma unroll
            for (int ks = 0; ks < 4; ks++) {
                uint32_t off = a_r * 128 + ((((ks << 1) | a_k) ^ a_x) << 4);
                ldsm_x4(qh[ks], sbase + ATT_QH + off);
                ldsm_x4(ql[ks], sbase + ATT_QL + off);
            }
        }

        const uint32_t st = sbase + ATT_STG0 + s * ATT_STG_BYTES;

        // ---- S = Q K^T (16 x 64 per warp), term-pass order ----
        float s_acc[8][4];
#pragma unroll
        for (int i = 0; i < 8; i++)
#pragma unroll
            for (int j = 0; j < 4; j++) s_acc[i][j] = 0.0f;

#pragma unroll
        for (int ks = 0; ks < 4; ks++) {
            uint32_t bh[4][4], bl[4][4];
#pragma unroll
            for (int nf2 = 0; nf2 < 4; nf2++) {
                int r = k_r + nf2 * 16;
                uint32_t off = r * 128 + ((((ks << 1) | k_k) ^ (r & 7)) << 4);
                ldsm_x4(bh[nf2], st + ATT_KH + off);
                ldsm_x4(bl[nf2], st + ATT_KL + off);
            }
            // pass 1: qh*kh over 8 independent accumulators
#pragma unroll
            for (int nf = 0; nf < 8; nf++)
                mma_bf16(s_acc[nf], qh[ks], &bh[nf >> 1][(nf & 1) * 2]);
            // pass 2: ql*kh
#pragma unroll
            for (int nf = 0; nf < 8; nf++)
                mma_bf16(s_acc[nf], ql[ks], &bh[nf >> 1][(nf & 1) * 2]);
            // pass 3: qh*kl
#pragma unroll
            for (int nf = 0; nf < 8; nf++)
                mma_bf16(s_acc[nf], qh[ks], &bl[nf >> 1][(nf & 1) * 2]);
        }

        // ---- causal mask (diagonal tile only) ----
        if (kb == qb) {
            const int qpos0 = q0 + w * 16 + (lane >> 2);
            const int kbase = k0 + (lane & 3) * 2;
#pragma unroll
            for (int nf = 0; nf < 8; nf++) {
                const int kp = kbase + nf * 8;
                if (kp     > qpos0)     s_acc[nf][0] = NEG_INF;
                if (kp + 1 > qpos0)     s_acc[nf][1] = NEG_INF;
                if (kp     > qpos0 + 8) s_acc[nf][2] = NEG_INF;
                if (kp + 1 > qpos0 + 8) s_acc[nf][3] = NEG_INF;
            }
        }

        // ---- online softmax (register-level, quad reduce) ----
#pragma unroll
        for (int half = 0; half < 2; half++) {
            float mx = NEG_INF;
#pragma unroll
            for (int nf = 0; nf < 8; nf++)
                mx = fmaxf(mx, fmaxf(s_acc[nf][half * 2], s_acc[nf][half * 2 + 1]));
            mx = fmaxf(mx, __shfl_xor_sync(0xffffffffu, mx, 1));
            mx = fmaxf(mx, __shfl_xor_sync(0xffffffffu, mx, 2));

            const float mnew  = fmaxf(m_run[half], mx);
            const float alpha = __expf(m_run[half] - mnew);
            m_run[half] = mnew;

            float sum = 0.0f;
#pragma unroll
            for (int nf = 0; nf < 8; nf++) {
                float p0 = __expf(s_acc[nf][half * 2]     - mnew);
                float p1 = __expf(s_acc[nf][half * 2 + 1] - mnew);
                s_acc[nf][half * 2]     = p0;
                s_acc[nf][half * 2 + 1] = p1;
                sum += p0 + p1;
            }
            sum += __shfl_xor_sync(0xffffffffu, sum, 1);
            sum += __shfl_xor_sync(0xffffffffu, sum, 2);
            l_run[half] = l_run[half] * alpha + sum;

#pragma unroll
            for (int dn = 0; dn < 8; dn++) {
                acc_o[dn][half * 2]     *= alpha;
                acc_o[dn][half * 2 + 1] *= alpha;
            }
        }

        // ---- O += P V, term-pass order over 8 independent accumulators ----
#pragma unroll
        for (int kc = 0; kc < 4; kc++) {
            uint32_t ah[4], al[4];
#pragma unroll
            for (int q = 0; q < 2; q++) {
                const float* sc = s_acc[2 * kc + q];
                float h0 = bfhi(sc[0]), h1 = bfhi(sc[1]);
                float h2 = bfhi(sc[2]), h3 = bfhi(sc[3]);
                ah[q * 2 + 0] = bf2pack(h0, h1);
                ah[q * 2 + 1] = bf2pack(h2, h3);
                al[q * 2 + 0] = bf2pack(sc[0] - h0, sc[1] - h1);
                al[q * 2 + 1] = bf2pack(sc[2] - h2, sc[3] - h3);
            }
            uint32_t vh[4][4], vl[4][4];
#pragma unroll
            for (int dg = 0; dg < 4; dg++) {
                int r = v_r + kc * 16;
                int ch = v_c + dg * 2;
                uint32_t off = r * 128 + ((ch ^ (r & 7)) << 4);
                ldsm_x4_t(vh[dg], st + ATT_VH + off);
                ldsm_x4_t(vl[dg], st + ATT_VL + off);
            }
            // pass 1: ph*vh
#pragma unroll
            for (int dg = 0; dg < 4; dg++)
#pragma unroll
                for (int q = 0; q < 2; q++)
                    mma_bf16(acc_o[dg * 2 + q], ah, &vh[dg][q * 2]);
            // pass 2: pl*vh
#pragma unroll
            for (int dg = 0; dg < 4; dg++)
#pragma unroll
                for (int q = 0; q < 2; q++)
                    mma_bf16(acc_o[dg * 2 + q], al, &vh[dg][q * 2]);
            // pass 3: ph*vl
#pragma unroll
            for (int dg = 0; dg < 4; dg++)
#pragma unroll
                for (int q = 0; q < 2; q++)
                    mma_bf16(acc_o[dg * 2 + q], ah, &vl[dg][q * 2]);
        }
        __syncthreads();
        s = (s + 1) % ATT_NSTG;
    }

    // ---- epilogue: normalize, split, store token-major [MTOT][DIM] ----
    const float inv0 = 1.0f / l_run[0];
    const float inv1 = 1.0f / l_run[1];
    const int row0 = q0 + w * 16 + (lane >> 2);
    const size_t tok0 = (size_t)(b * SEQ + row0) * DIM + h * HDIM;
    const size_t tok1 = tok0 + 8 * DIM;
#pragma unroll
    for (int dn = 0; dn < 8; dn++) {
        const int d = dn * 8 + (lane & 3) * 2;
        float f0 = acc_o[dn][0] * inv0;
        float f1 = acc_o[dn][1] * inv0;
        float f2 = acc_o[dn][2] * inv1;
        float f3 = acc_o[dn][3] * inv1;
        unsigned short h0, l0, h1, l1, h2, l2, h3, l3;
        split1(f0, h0, l0); split1(f1, h1, l1);
        split1(f2, h2, l2); split1(f3, h3, l3);
        *(ushort2*)(g_o_hi + tok0 + d) = make_ushort2(h0, h1);
        *(ushort2*)(g_o_lo + tok0 + d) = make_ushort2(l0, l1);
        *(ushort2*)(g_o_hi + tok1 + d) = make_ushort2(h2, h3);
        *(ushort2*)(g_o_lo + tok1 + d) = make_ushort2(l2, l3);
    }
}

// ============================================================================
// launch
// ============================================================================
extern "C" void kernel_launch(void* const* d_in, const int* in_sizes, int n_in,
                              void* d_out, int out_size)
{
    const float* x  = (const float*)d_in[0];
    const float* Wq = (const float*)d_in[1];
    const float* Wk = (const float*)d_in[2];
    const float* Wv = (const float*)d_in[3];
    const float* Wo = (const float*)d_in[4];
    const float* bo = (const float*)d_in[5];
    float* out = (float*)d_out;

    cudaFuncSetAttribute(gemm_qkv_bf16,  cudaFuncAttributeMaxDynamicSharedMemorySize, GEMM_SMEM);
    cudaFuncSetAttribute(gemm_out_bf16,  cudaFuncAttributeMaxDynamicSharedMemorySize, GEMM_SMEM);
    cudaFuncSetAttribute(attn_mma_kernel, cudaFuncAttributeMaxDynamicSharedMemorySize, ATT_SMEM);

    // fused bf16 hi/lo splits (MLP=4 per thread)
    split_all_kernel<<<2048, 256>>>(x, Wq, Wk, Wv, Wo);

    // QKV projections -> head-major bf16 hi/lo (Q pre-scaled)
    dim3 gridQKV(DIM / 64, MTOT / 128, 3);
    gemm_qkv_bf16<<<gridQKV, 256, GEMM_SMEM>>>();

    // tensor-core flash attention (BQ=64, 3-stage KV ring, 2 CTAs/SM)
    dim3 gridAtt(SEQ / 64, NHEADS, BATCH);
    attn_mma_kernel<<<gridAtt, 128, ATT_SMEM>>>();

    // output projection + bias
    dim3 gridOut(DIM / 64, MTOT / 128);
    gemm_out_bf16<<<gridOut, 256, GEMM_SMEM>>>(bo, out);
}

// round 13
// speedup vs baseline: 1.1345x; 1.1238x over previous
#include <cuda_runtime.h>
#include <cuda_bf16.h>
#include <cuda_fp16.h>
#include <math.h>
#include <stdint.h>

#define DIM    1024
#define NHEADS 16
#define HDIM   64
#define BATCH  2
#define SEQ    2048
#define MTOT   (BATCH * SEQ)   // 4096

// ---------------- scratch (static device globals; no allocation) ----------------
__device__ unsigned short g_x_hi[MTOT * DIM];          // bf16
__device__ unsigned short g_x_lo[MTOT * DIM];          // bf16
__device__ unsigned short g_w_hi[4 * DIM * DIM];       // bf16: Wq, Wk, Wv, Wo
__device__ unsigned short g_w_lo[4 * DIM * DIM];       // bf16
// Q hi/lo fp16 (2-term corrected side); K/V fp16 hi only. Head-major [B][H][T][D].
__device__ unsigned short g_q_hi[MTOT * DIM];
__device__ unsigned short g_q_lo[MTOT * DIM];
__device__ unsigned short g_k_hi[MTOT * DIM];
__device__ unsigned short g_v_hi[MTOT * DIM];
// attention output, token-major [MTOT][DIM], bf16 hi/lo (for bf16x3 out-proj)
__device__ unsigned short g_o_hi[MTOT * DIM];
__device__ unsigned short g_o_lo[MTOT * DIM];

// ============================================================================
// helpers
// ============================================================================
__device__ __forceinline__ void split1(float v, unsigned short& h, unsigned short& l)
{
    __nv_bfloat16 hb = __float2bfloat16(v);
    h = __bfloat16_as_ushort(hb);
    l = __bfloat16_as_ushort(__float2bfloat16(v - __bfloat162float(hb)));
}
__device__ __forceinline__ void split4(const float4 v, ushort4& h, ushort4& l)
{
    split1(v.x, h.x, l.x);
    split1(v.y, h.y, l.y);
    split1(v.z, h.z, l.z);
    split1(v.w, h.w, l.w);
}
// fp16 split
__device__ __forceinline__ void split1h(float v, unsigned short& h, unsigned short& l)
{
    __half hh = __float2half_rn(v);
    h = __half_as_ushort(hh);
    l = __half_as_ushort(__float2half_rn(v - __half2float(hh)));
}
__device__ __forceinline__ uint32_t h2pack(float a, float b)
{
    __half2 t = __floats2half2_rn(a, b);
    return *reinterpret_cast<uint32_t*>(&t);
}
__device__ __forceinline__ float h_hi(float v)
{
    return __half2float(__float2half_rn(v));
}

// fused split, 4 independent float4s per thread (MLP=4).
__global__ void split_all_kernel(const float* __restrict__ x,
                                 const float* __restrict__ Wq,
                                 const float* __restrict__ Wk,
                                 const float* __restrict__ Wv,
                                 const float* __restrict__ Wo)
{
    const int blk = blockIdx.x;
    if (blk < 1024) {
        int base = blk * 1024 + threadIdx.x;
#pragma unroll
        for (int j = 0; j < 4; j++) {
            int i = base + j * 256;
            float4 v = ((const float4*)x)[i];
            ushort4 h, l;
            split4(v, h, l);
            ((ushort4*)g_x_hi)[i] = h;
            ((ushort4*)g_x_lo)[i] = l;
        }
    } else {
        int wbase = (blk - 1024) * 1024 + threadIdx.x;
#pragma unroll
        for (int j = 0; j < 4; j++) {
            int widx = wbase + j * 256;
            int z = widx >> 18;
            int i = widx & 262143;
            const float* w = (z == 0) ? Wq : (z == 1) ? Wk : (z == 2) ? Wv : Wo;
            float4 v = ((const float4*)w)[i];
            ushort4 h, l;
            split4(v, h, l);
            ((ushort4*)g_w_hi)[(size_t)z * 262144 + i] = h;
            ((ushort4*)g_w_lo)[(size_t)z * 262144 + i] = l;
        }
    }
}

// ============================================================================
// async / mma primitives
// ============================================================================
__device__ __forceinline__ void cp16(uint32_t dst, const void* src)
{
    asm volatile("cp.async.cg.shared.global [%0], [%1], 16;\n" :: "r"(dst), "l"(src));
}
__device__ __forceinline__ void cp_commit()
{
    asm volatile("cp.async.commit_group;\n");
}
template<int N> __device__ __forceinline__ void cp_wait()
{
    asm volatile("cp.async.wait_group %0;\n" :: "n"(N));
}
__device__ __forceinline__ void ldsm_x4(uint32_t* r, uint32_t addr)
{
    asm volatile("ldmatrix.sync.aligned.m8n8.x4.shared.b16 {%0,%1,%2,%3}, [%4];"
                 : "=r"(r[0]), "=r"(r[1]), "=r"(r[2]), "=r"(r[3]) : "r"(addr));
}
__device__ __forceinline__ void ldsm_x4_t(uint32_t* r, uint32_t addr)
{
    asm volatile("ldmatrix.sync.aligned.m8n8.x4.trans.shared.b16 {%0,%1,%2,%3}, [%4];"
                 : "=r"(r[0]), "=r"(r[1]), "=r"(r[2]), "=r"(r[3]) : "r"(addr));
}
__device__ __forceinline__ void mma_bf16(float* c, const uint32_t* a, const uint32_t* b)
{
    asm volatile("mma.sync.aligned.m16n8k16.row.col.f32.bf16.bf16.f32 "
                 "{%0,%1,%2,%3},{%4,%5,%6,%7},{%8,%9},{%0,%1,%2,%3};"
                 : "+f"(c[0]), "+f"(c[1]), "+f"(c[2]), "+f"(c[3])
                 : "r"(a[0]), "r"(a[1]), "r"(a[2]), "r"(a[3]), "r"(b[0]), "r"(b[1]));
}
__device__ __forceinline__ void mma_f16(float* c, const uint32_t* a, const uint32_t* b)
{
    asm volatile("mma.sync.aligned.m16n8k16.row.col.f32.f16.f16.f32 "
                 "{%0,%1,%2,%3},{%4,%5,%6,%7},{%8,%9},{%0,%1,%2,%3};"
                 : "+f"(c[0]), "+f"(c[1]), "+f"(c[2]), "+f"(c[3])
                 : "r"(a[0]), "r"(a[1]), "r"(a[2]), "r"(a[3]), "r"(b[0]), "r"(b[1]));
}

// ============================================================================
// bf16x3 tensor-core GEMM:  C[M,N] = A[M,K] * B[N,K]^T  (R12 config, unchanged)
// BM=128, BN=64, BK=64, 256 threads (8 warps: 4m x 2n), 2-stage cp.async,
// 2 CTAs/SM.
// MODE 0: Q -> fp16 hi/lo split, scaled, head-major.  (Clo != null)
//         K/V -> fp16 hi only, head-major.            (Clo == null)
// MODE 1: fp32 + bias.
// ============================================================================
#define STG_BYTES 49152
#define AH_OFF 0
#define AL_OFF 16384
#define BH_OFF 32768
#define BL_OFF 40960
#define GEMM_SMEM (2 * STG_BYTES)

template<int MODE>
__device__ __forceinline__ void gemm_bf16_body(
    const unsigned short* __restrict__ Ah, const unsigned short* __restrict__ Al,
    const unsigned short* __restrict__ Bh, const unsigned short* __restrict__ Bl,
    float scale,
    unsigned short* __restrict__ Chi, unsigned short* __restrict__ Clo,
    const float* __restrict__ bias, float* __restrict__ C)
{
    extern __shared__ char dsm[];
    const uint32_t sbase = (uint32_t)__cvta_generic_to_shared(dsm);

    const int tid  = threadIdx.x;
    const int bm   = blockIdx.y * 128;
    const int bn   = blockIdx.x * 64;
    const int lane = tid & 31;
    const int warp = tid >> 5;
    const int wm   = warp & 3;
    const int wn   = warp >> 2;

    auto load_stage = [&](int s, int k0) {
        const uint32_t sb = sbase + s * STG_BYTES;
#pragma unroll
        for (int t = 0; t < 4; t++) {
            int c   = tid + t * 256;
            int row = c >> 3, ch = c & 7;
            size_t   gofs = (size_t)(bm + row) * DIM + k0 + ch * 8;
            uint32_t sofs = row * 128 + ((ch ^ (row & 7)) << 4);
            cp16(sb + AH_OFF + sofs, Ah + gofs);
            cp16(sb + AL_OFF + sofs, Al + gofs);
        }
#pragma unroll
        for (int t = 0; t < 2; t++) {
            int c   = tid + t * 256;
            int row = c >> 3, ch = c & 7;
            size_t   gofs = (size_t)(bn + row) * DIM + k0 + ch * 8;
            uint32_t sofs = row * 128 + ((ch ^ (row & 7)) << 4);
            cp16(sb + BH_OFF + sofs, Bh + gofs);
            cp16(sb + BL_OFF + sofs, Bl + gofs);
        }
    };

    float acc[2][4][4];
#pragma unroll
    for (int i = 0; i < 2; i++)
#pragma unroll
        for (int j = 0; j < 4; j++)
#pragma unroll
            for (int k = 0; k < 4; k++) acc[i][j][k] = 0.0f;

    const int a_r = wm * 32 + (lane & 15);
    const int a_k = (lane >> 4);
    const int a_x = a_r & 7;
    const int b_r = wn * 32 + (lane & 7) + ((lane >> 4) << 3);
    const int b_k = (lane >> 3) & 1;
    const int b_x = b_r & 7;

    load_stage(0, 0);
    cp_commit();

    constexpr int NIT = DIM / 64;   // 16
    for (int it = 0; it < NIT; ++it) {
        const int s = it & 1;
        if (it + 1 < NIT) {
            load_stage(s ^ 1, (it + 1) * 64);
            cp_commit();
            cp_wait<1>();
        } else {
            cp_wait<0>();
        }
        __syncthreads();

        const uint32_t sb = sbase + s * STG_BYTES;
#pragma unroll
        for (int ks = 0; ks < 4; ks++) {
            uint32_t ah[2][4], al[2][4], bh[2][4], bl[2][4];
#pragma unroll
            for (int mf = 0; mf < 2; mf++) {
                uint32_t off = (a_r + mf * 16) * 128 + ((((ks << 1) | a_k) ^ a_x) << 4);
                ldsm_x4(ah[mf], sb + AH_OFF + off);
                ldsm_x4(al[mf], sb + AL_OFF + off);
            }
#pragma unroll
            for (int nf2 = 0; nf2 < 2; nf2++) {
                uint32_t off = (b_r + nf2 * 16) * 128 + ((((ks << 1) | b_k) ^ b_x) << 4);
                ldsm_x4(bh[nf2], sb + BH_OFF + off);
                ldsm_x4(bl[nf2], sb + BL_OFF + off);
            }
#pragma unroll
            for (int mf = 0; mf < 2; mf++)
#pragma unroll
                for (int nf = 0; nf < 4; nf++)
                    mma_bf16(acc[mf][nf], ah[mf], &bh[nf >> 1][(nf & 1) * 2]);
#pragma unroll
            for (int mf = 0; mf < 2; mf++)
#pragma unroll
                for (int nf = 0; nf < 4; nf++)
                    mma_bf16(acc[mf][nf], al[mf], &bh[nf >> 1][(nf & 1) * 2]);
#pragma unroll
            for (int mf = 0; mf < 2; mf++)
#pragma unroll
                for (int nf = 0; nf < 4; nf++)
                    mma_bf16(acc[mf][nf], ah[mf], &bl[nf >> 1][(nf & 1) * 2]);
        }
        __syncthreads();
    }

    // epilogue
#pragma unroll
    for (int mf = 0; mf < 2; mf++) {
        const int row0 = bm + wm * 32 + mf * 16 + (lane >> 2);
#pragma unroll
        for (int nf = 0; nf < 4; nf++) {
            const int col = bn + wn * 32 + nf * 8 + (lane & 3) * 2;
            if (MODE == 0) {
                const int h = col >> 6, d = col & 63;
#pragma unroll
                for (int half = 0; half < 2; half++) {
                    const int row = row0 + half * 8;
                    const int b = row >> 11, t = row & 2047;
                    const size_t dst = (((size_t)(b * NHEADS + h) * SEQ) + t) * HDIM + d;
                    float f0 = acc[mf][nf][half * 2 + 0] * scale;
                    float f1 = acc[mf][nf][half * 2 + 1] * scale;
                    if (Clo) {
                        unsigned short h0, l0, h1, l1;
                        split1h(f0, h0, l0);
                        split1h(f1, h1, l1);
                        *(ushort2*)(Chi + dst) = make_ushort2(h0, h1);
                        *(ushort2*)(Clo + dst) = make_ushort2(l0, l1);
                    } else {
                        __half2 p = __floats2half2_rn(f0, f1);
                        *(uint32_t*)(Chi + dst) = *reinterpret_cast<uint32_t*>(&p);
                    }
                }
            } else {
                float b0 = bias[col], b1 = bias[col + 1];
                float2 v0 = make_float2(acc[mf][nf][0] + b0, acc[mf][nf][1] + b1);
                float2 v1 = make_float2(acc[mf][nf][2] + b0, acc[mf][nf][3] + b1);
                *(float2*)(C + (size_t)row0 * DIM + col)       = v0;
                *(float2*)(C + (size_t)(row0 + 8) * DIM + col) = v1;
            }
        }
    }
}

__global__ void __launch_bounds__(256, 2) gemm_qkv_bf16()
{
    const int z = blockIdx.z;
    unsigned short* Chi = (z == 0) ? g_q_hi : (z == 1) ? g_k_hi : g_v_hi;
    unsigned short* Clo = (z == 0) ? g_q_lo : nullptr;
    const float scale = (z == 0) ? 0.125f : 1.0f;
    gemm_bf16_body<0>(g_x_hi, g_x_lo,
                      g_w_hi + (size_t)z * DIM * DIM, g_w_lo + (size_t)z * DIM * DIM,
                      scale, Chi, Clo, nullptr, nullptr);
}

__global__ void __launch_bounds__(256, 2) gemm_out_bf16(
    const float* __restrict__ bo, float* __restrict__ out)
{
    gemm_bf16_body<1>(g_o_hi, g_o_lo,
                      g_w_hi + (size_t)3 * DIM * DIM, g_w_lo + (size_t)3 * DIM * DIM,
                      1.0f, nullptr, nullptr, bo, out);
}

// ============================================================================
// Tensor-core flash attention, fp16 2-term (causal).
// S = Qh*Kh + Ql*Kh (K fp16-hi).  O = Ph*Vh + Pl*Vh (V fp16-hi).
// BQ=64: 128 threads (4 warps x 16 q-rows), BK=64, 3-stage KV ring.
// smem 64KB -> up to 3 CTAs/SM.
// ============================================================================
#define ATT_QH 0
#define ATT_QL 8192
#define ATT_STG0 16384
#define ATT_STG_BYTES 16384       // KH 8K | VH 8K
#define ATT_KH 0
#define ATT_VH 8192
#define ATT_NSTG 3
#define ATT_SMEM (ATT_STG0 + ATT_NSTG * ATT_STG_BYTES)   // 65536

#define NEG_INF __int_as_float(0xff800000)

__global__ void __launch_bounds__(128, 1) attn_mma_kernel()
{
    extern __shared__ char dsm[];
    const uint32_t sbase = (uint32_t)__cvta_generic_to_shared(dsm);

    const int tid  = threadIdx.x;
    const int lane = tid & 31;
    const int w    = tid >> 5;           // 0..3
    const int qb   = (gridDim.x - 1) - blockIdx.x;   // big tiles first
    const int h    = blockIdx.y;
    const int b    = blockIdx.z;
    const int q0   = qb * 64;

    const size_t head = (size_t)(b * NHEADS + h) * SEQ * HDIM;
    const unsigned short* Qh = g_q_hi + head;
    const unsigned short* Ql = g_q_lo + head;
    const unsigned short* Kh = g_k_hi + head;
    const unsigned short* Vh = g_v_hi + head;

    // ---- load Q tile (64 rows x 64 fp16, hi+lo) ----
#pragma unroll
    for (int t = 0; t < 4; t++) {
        int c = tid + t * 128;           // 0..511
        int row = c >> 3, ch = c & 7;
        size_t   g = (size_t)(q0 + row) * HDIM + ch * 8;
        uint32_t sofs = row * 128 + ((ch ^ (row & 7)) << 4);
        cp16(sbase + ATT_QH + sofs, Qh + g);
        cp16(sbase + ATT_QL + sofs, Ql + g);
    }

    auto load_kv = [&](int s, int k0) {
        const uint32_t st = sbase + ATT_STG0 + s * ATT_STG_BYTES;
#pragma unroll
        for (int t = 0; t < 4; t++) {
            int c = tid + t * 128;       // 0..511
            int row = c >> 3, ch = c & 7;
            size_t   g = (size_t)(k0 + row) * HDIM + ch * 8;
            uint32_t sofs = row * 128 + ((ch ^ (row & 7)) << 4);
            cp16(st + ATT_KH + sofs, Kh + g);
            cp16(st + ATT_VH + sofs, Vh + g);
        }
    };

    const int kmax = qb;

    load_kv(0, 0);
    cp_commit();
    if (kmax >= 1) {
        load_kv(1, 64);
        cp_commit();
    }

    const int a_r = w * 16 + (lane & 15);
    const int a_k = lane >> 4;
    const int a_x = a_r & 7;
    const int k_r = (lane & 7) + ((lane >> 4) << 3);
    const int k_k = (lane >> 3) & 1;
    const int v_r = (lane & 7) + (((lane >> 3) & 1) << 3);
    const int v_c = lane >> 4;

    uint32_t qh[4][4], ql[4][4];

    float m_run[2] = {NEG_INF, NEG_INF};
    float l_run[2] = {0.0f, 0.0f};
    float acc_o[8][4];
#pragma unroll
    for (int i = 0; i < 8; i++)
#pragma unroll
        for (int j = 0; j < 4; j++) acc_o[i][j] = 0.0f;

    int s = 0;
    for (int kb = 0; kb <= kmax; kb++) {
        const int k0 = kb * 64;
        if (kb + 2 <= kmax) {
            load_kv((s + 2) % ATT_NSTG, (kb + 2) * 64);
            cp_commit();
            cp_wait<2>();
        } else if (kb + 1 <= kmax) {
            cp_wait<1>();
        } else {
            cp_wait<0>();
        }
        __syncthreads();

        if (kb == 0) {
#pragma unroll
            for (int ks = 0; ks < 4; ks++) {
                uint32_t off = a_r * 128 + ((((ks << 1) | a_k) ^ a_x) << 4);
                ldsm_x4(qh[ks], sbase + ATT_QH + off);
                ldsm_x4(ql[ks], sbase + ATT_QL + off);
            }
        }

        const uint32_t st = sbase + ATT_STG0 + s * ATT_STG_BYTES;

        // ---- S = Q K^T (16 x 64 per warp), 2 fp16 terms ----
        float s_acc[8][4];
#pragma unroll
        for (int i = 0; i < 8; i++)
#pragma unroll
            for (int j = 0; j < 4; j++) s_acc[i][j] = 0.0f;

#pragma unroll
        for (int ks = 0; ks < 4; ks++) {
            uint32_t bh[4][4];
#pragma unroll
            for (int nf2 = 0; nf2 < 4; nf2++) {
                int r = k_r + nf2 * 16;
                uint32_t off = r * 128 + ((((ks << 1) | k_k) ^ (r & 7)) << 4);
                ldsm_x4(bh[nf2], st + ATT_KH + off);
            }
#pragma unroll
            for (int nf = 0; nf < 8; nf++)
                mma_f16(s_acc[nf], qh[ks], &bh[nf >> 1][(nf & 1) * 2]);
#pragma unroll
            for (int nf = 0; nf < 8; nf++)
                mma_f16(s_acc[nf], ql[ks], &bh[nf >> 1][(nf & 1) * 2]);
        }

        // ---- causal mask (diagonal tile only) ----
        if (kb == qb) {
            const int qpos0 = q0 + w * 16 + (lane >> 2);
            const int kbase = k0 + (lane & 3) * 2;
#pragma unroll
            for (int nf = 0; nf < 8; nf++) {
                const int kp = kbase + nf * 8;
                if (kp     > qpos0)     s_acc[nf][0] = NEG_INF;
                if (kp + 1 > qpos0)     s_acc[nf][1] = NEG_INF;
                if (kp     > qpos0 + 8) s_acc[nf][2] = NEG_INF;
                if (kp + 1 > qpos0 + 8) s_acc[nf][3] = NEG_INF;
            }
        }

        // ---- online softmax (register-level, quad reduce) ----
#pragma unroll
        for (int half = 0; half < 2; half++) {
            float mx = NEG_INF;
#pragma unroll
            for (int nf = 0; nf < 8; nf++)
                mx = fmaxf(mx, fmaxf(s_acc[nf][half * 2], s_acc[nf][half * 2 + 1]));
            mx = fmaxf(mx, __shfl_xor_sync(0xffffffffu, mx, 1));
            mx = fmaxf(mx, __shfl_xor_sync(0xffffffffu, mx, 2));

            const float mnew  = fmaxf(m_run[half], mx);
            const float alpha = __expf(m_run[half] - mnew);
            m_run[half] = mnew;

            float sum = 0.0f;
#pragma unroll
            for (int nf = 0; nf < 8; nf++) {
                float p0 = __expf(s_acc[nf][half * 2]     - mnew);
                float p1 = __expf(s_acc[nf][half * 2 + 1] - mnew);
                s_acc[nf][half * 2]     = p0;
                s_acc[nf][half * 2 + 1] = p1;
                sum += p0 + p1;
            }
            sum += __shfl_xor_sync(0xffffffffu, sum, 1);
            sum += __shfl_xor_sync(0xffffffffu, sum, 2);
            l_run[half] = l_run[half] * alpha + sum;

#pragma unroll
            for (int dn = 0; dn < 8; dn++) {
                acc_o[dn][half * 2]     *= alpha;
                acc_o[dn][half * 2 + 1] *= alpha;
            }
        }

        // ---- O += P V, 2 fp16 terms (P split hi/lo; V hi only) ----
#pragma unroll
        for (int kc = 0; kc < 4; kc++) {
            uint32_t ah[4], al[4];
#pragma unroll
            for (int q = 0; q < 2; q++) {
                const float* sc = s_acc[2 * kc + q];
                float h0 = h_hi(sc[0]), h1 = h_hi(sc[1]);
                float h2 = h_hi(sc[2]), h3 = h_hi(sc[3]);
                ah[q * 2 + 0] = h2pack(h0, h1);
                ah[q * 2 + 1] = h2pack(h2, h3);
                al[q * 2 + 0] = h2pack(sc[0] - h0, sc[1] - h1);
                al[q * 2 + 1] = h2pack(sc[2] - h2, sc[3] - h3);
            }
            uint32_t vh[4][4];
#pragma unroll
            for (int dg = 0; dg < 4; dg++) {
                int r = v_r + kc * 16;
                int ch = v_c + dg * 2;
                uint32_t off = r * 128 + ((ch ^ (r & 7)) << 4);
                ldsm_x4_t(vh[dg], st + ATT_VH + off);
            }
#pragma unroll
            for (int dg = 0; dg < 4; dg++)
#pragma unroll
                for (int q = 0; q < 2; q++)
                    mma_f16(acc_o[dg * 2 + q], ah, &vh[dg][q * 2]);
#pragma unroll
            for (int dg = 0; dg < 4; dg++)
#pragma unroll
                for (int q = 0; q < 2; q++)
                    mma_f16(acc_o[dg * 2 + q], al, &vh[dg][q * 2]);
        }
        __syncthreads();
        s = (s + 1) % ATT_NSTG;
    }

    // ---- epilogue: normalize, split (bf16 for out-proj), store token-major ----
    const float inv0 = 1.0f / l_run[0];
    const float inv1 = 1.0f / l_run[1];
    const int row0 = q0 + w * 16 + (lane >> 2);
    const size_t tok0 = (size_t)(b * SEQ + row0) * DIM + h * HDIM;
    const size_t tok1 = tok0 + 8 * DIM;
#pragma unroll
    for (int dn = 0; dn < 8; dn++) {
        const int d = dn * 8 + (lane & 3) * 2;
        float f0 = acc_o[dn][0] * inv0;
        float f1 = acc_o[dn][1] * inv0;
        float f2 = acc_o[dn][2] * inv1;
        float f3 = acc_o[dn][3] * inv1;
        unsigned short h0, l0, h1, l1, h2, l2, h3, l3;
        split1(f0, h0, l0); split1(f1, h1, l1);
        split1(f2, h2, l2); split1(f3, h3, l3);
        *(ushort2*)(g_o_hi + tok0 + d) = make_ushort2(h0, h1);
        *(ushort2*)(g_o_lo + tok0 + d) = make_ushort2(l0, l1);
        *(ushort2*)(g_o_hi + tok1 + d) = make_ushort2(h2, h3);
        *(ushort2*)(g_o_lo + tok1 + d) = make_ushort2(l2, l3);
    }
}

// ============================================================================
// launch
// ============================================================================
extern "C" void kernel_launch(void* const* d_in, const int* in_sizes, int n_in,
                              void* d_out, int out_size)
{
    const float* x  = (const float*)d_in[0];
    const float* Wq = (const float*)d_in[1];
    const float* Wk = (const float*)d_in[2];
    const float* Wv = (const float*)d_in[3];
    const float* Wo = (const float*)d_in[4];
    const float* bo = (const float*)d_in[5];
    float* out = (float*)d_out;

    cudaFuncSetAttribute(gemm_qkv_bf16,  cudaFuncAttributeMaxDynamicSharedMemorySize, GEMM_SMEM);
    cudaFuncSetAttribute(gemm_out_bf16,  cudaFuncAttributeMaxDynamicSharedMemorySize, GEMM_SMEM);
    cudaFuncSetAttribute(attn_mma_kernel, cudaFuncAttributeMaxDynamicSharedMemorySize, ATT_SMEM);

    // fused bf16 hi/lo splits (MLP=4 per thread)
    split_all_kernel<<<2048, 256>>>(x, Wq, Wk, Wv, Wo);

    // QKV projections -> Q fp16 hi/lo (pre-scaled), K/V fp16 hi; head-major
    dim3 gridQKV(DIM / 64, MTOT / 128, 3);
    gemm_qkv_bf16<<<gridQKV, 256, GEMM_SMEM>>>();

    // fp16 2-term flash attention (BQ=64, 3-stage KV ring)
    dim3 gridAtt(SEQ / 64, NHEADS, BATCH);
    attn_mma_kernel<<<gridAtt, 128, ATT_SMEM>>>();

    // output projection + bias (bf16x3)
    dim3 gridOut(DIM / 64, MTOT / 128);
    gemm_out_bf16<<<gridOut, 256, GEMM_SMEM>>>(bo, out);
}

// round 14
// speedup vs baseline: 1.3827x; 1.2187x over previous
#include <cuda_runtime.h>
#include <cuda_bf16.h>
#include <cuda_fp16.h>
#include <math.h>
#include <stdint.h>

#define DIM    1024
#define NHEADS 16
#define HDIM   64
#define BATCH  2
#define SEQ    2048
#define MTOT   (BATCH * SEQ)   // 4096

// ---------------- scratch (static device globals; no allocation) ----------------
// fp16 everywhere: x hi/lo, W hi only
__device__ unsigned short g_x_hi[MTOT * DIM];
__device__ unsigned short g_x_lo[MTOT * DIM];
__device__ unsigned short g_w_hi[4 * DIM * DIM];       // Wq, Wk, Wv, Wo (fp16 hi)
// Q hi/lo fp16; K/V fp16 hi only. Head-major [B][H][T][D].
__device__ unsigned short g_q_hi[MTOT * DIM];
__device__ unsigned short g_q_lo[MTOT * DIM];
__device__ unsigned short g_k_hi[MTOT * DIM];
__device__ unsigned short g_v_hi[MTOT * DIM];
// attention output, token-major [MTOT][DIM], fp16 hi/lo
__device__ unsigned short g_o_hi[MTOT * DIM];
__device__ unsigned short g_o_lo[MTOT * DIM];

// ============================================================================
// helpers (fp16 split)
// ============================================================================
__device__ __forceinline__ void split1h(float v, unsigned short& h, unsigned short& l)
{
    __half hh = __float2half_rn(v);
    h = __half_as_ushort(hh);
    l = __half_as_ushort(__float2half_rn(v - __half2float(hh)));
}
__device__ __forceinline__ uint32_t h2pack(float a, float b)
{
    __half2 t = __floats2half2_rn(a, b);
    return *reinterpret_cast<uint32_t*>(&t);
}
__device__ __forceinline__ float h_hi(float v)
{
    return __half2float(__float2half_rn(v));
}

// fused split, 4 independent float4s per thread (MLP=4).
// blocks 0..1023: x -> fp16 hi/lo. blocks 1024..2047: W -> fp16 hi only.
__global__ void split_all_kernel(const float* __restrict__ x,
                                 const float* __restrict__ Wq,
                                 const float* __restrict__ Wk,
                                 const float* __restrict__ Wv,
                                 const float* __restrict__ Wo)
{
    const int blk = blockIdx.x;
    if (blk < 1024) {
        int base = blk * 1024 + threadIdx.x;
#pragma unroll
        for (int j = 0; j < 4; j++) {
            int i = base + j * 256;
            float4 v = ((const float4*)x)[i];
            ushort4 h, l;
            split1h(v.x, h.x, l.x);
            split1h(v.y, h.y, l.y);
            split1h(v.z, h.z, l.z);
            split1h(v.w, h.w, l.w);
            ((ushort4*)g_x_hi)[i] = h;
            ((ushort4*)g_x_lo)[i] = l;
        }
    } else {
        int wbase = (blk - 1024) * 1024 + threadIdx.x;
#pragma unroll
        for (int j = 0; j < 4; j++) {
            int widx = wbase + j * 256;
            int z = widx >> 18;
            int i = widx & 262143;
            const float* w = (z == 0) ? Wq : (z == 1) ? Wk : (z == 2) ? Wv : Wo;
            float4 v = ((const float4*)w)[i];
            __half2 p0 = __floats2half2_rn(v.x, v.y);
            __half2 p1 = __floats2half2_rn(v.z, v.w);
            uint2 packed = make_uint2(*reinterpret_cast<uint32_t*>(&p0),
                                      *reinterpret_cast<uint32_t*>(&p1));
            ((uint2*)g_w_hi)[(size_t)z * 262144 + i] = packed;
        }
    }
}

// ============================================================================
// async / mma primitives
// ============================================================================
__device__ __forceinline__ void cp16(uint32_t dst, const void* src)
{
    asm volatile("cp.async.cg.shared.global [%0], [%1], 16;\n" :: "r"(dst), "l"(src));
}
__device__ __forceinline__ void cp_commit()
{
    asm volatile("cp.async.commit_group;\n");
}
template<int N> __device__ __forceinline__ void cp_wait()
{
    asm volatile("cp.async.wait_group %0;\n" :: "n"(N));
}
__device__ __forceinline__ void ldsm_x4(uint32_t* r, uint32_t addr)
{
    asm volatile("ldmatrix.sync.aligned.m8n8.x4.shared.b16 {%0,%1,%2,%3}, [%4];"
                 : "=r"(r[0]), "=r"(r[1]), "=r"(r[2]), "=r"(r[3]) : "r"(addr));
}
__device__ __forceinline__ void ldsm_x4_t(uint32_t* r, uint32_t addr)
{
    asm volatile("ldmatrix.sync.aligned.m8n8.x4.trans.shared.b16 {%0,%1,%2,%3}, [%4];"
                 : "=r"(r[0]), "=r"(r[1]), "=r"(r[2]), "=r"(r[3]) : "r"(addr));
}
__device__ __forceinline__ void mma_f16(float* c, const uint32_t* a, const uint32_t* b)
{
    asm volatile("mma.sync.aligned.m16n8k16.row.col.f32.f16.f16.f32 "
                 "{%0,%1,%2,%3},{%4,%5,%6,%7},{%8,%9},{%0,%1,%2,%3};"
                 : "+f"(c[0]), "+f"(c[1]), "+f"(c[2]), "+f"(c[3])
                 : "r"(a[0]), "r"(a[1]), "r"(a[2]), "r"(a[3]), "r"(b[0]), "r"(b[1]));
}

// ============================================================================
// fp16 2-term tensor-core GEMM:  C = A*B^T ~= Ah*Bh + Al*Bh
// BM=128, BN=64, BK=64, 256 threads (8 warps: 4m x 2n), 2-stage cp.async,
// 2 CTAs/SM (80KB smem).
// MODE 0: Q -> fp16 hi/lo split (Clo!=null), K/V -> fp16 hi (Clo==null); head-major.
// MODE 1: fp32 + bias.
// ============================================================================
#define STG_BYTES 40960
#define AH_OFF 0
#define AL_OFF 16384
#define BH_OFF 32768
#define GEMM_SMEM (2 * STG_BYTES)   // 81920

template<int MODE>
__device__ __forceinline__ void gemm_f16_body(
    const unsigned short* __restrict__ Ah, const unsigned short* __restrict__ Al,
    const unsigned short* __restrict__ Bh,
    float scale,
    unsigned short* __restrict__ Chi, unsigned short* __restrict__ Clo,
    const float* __restrict__ bias, float* __restrict__ C)
{
    extern __shared__ char dsm[];
    const uint32_t sbase = (uint32_t)__cvta_generic_to_shared(dsm);

    const int tid  = threadIdx.x;
    const int bm   = blockIdx.y * 128;
    const int bn   = blockIdx.x * 64;
    const int lane = tid & 31;
    const int warp = tid >> 5;
    const int wm   = warp & 3;
    const int wn   = warp >> 2;

    auto load_stage = [&](int s, int k0) {
        const uint32_t sb = sbase + s * STG_BYTES;
#pragma unroll
        for (int t = 0; t < 4; t++) {
            int c   = tid + t * 256;
            int row = c >> 3, ch = c & 7;
            size_t   gofs = (size_t)(bm + row) * DIM + k0 + ch * 8;
            uint32_t sofs = row * 128 + ((ch ^ (row & 7)) << 4);
            cp16(sb + AH_OFF + sofs, Ah + gofs);
            cp16(sb + AL_OFF + sofs, Al + gofs);
        }
#pragma unroll
        for (int t = 0; t < 2; t++) {
            int c   = tid + t * 256;
            int row = c >> 3, ch = c & 7;
            size_t   gofs = (size_t)(bn + row) * DIM + k0 + ch * 8;
            uint32_t sofs = row * 128 + ((ch ^ (row & 7)) << 4);
            cp16(sb + BH_OFF + sofs, Bh + gofs);
        }
    };

    float acc[2][4][4];
#pragma unroll
    for (int i = 0; i < 2; i++)
#pragma unroll
        for (int j = 0; j < 4; j++)
#pragma unroll
            for (int k = 0; k < 4; k++) acc[i][j][k] = 0.0f;

    const int a_r = wm * 32 + (lane & 15);
    const int a_k = (lane >> 4);
    const int a_x = a_r & 7;
    const int b_r = wn * 32 + (lane & 7) + ((lane >> 4) << 3);
    const int b_k = (lane >> 3) & 1;
    const int b_x = b_r & 7;

    load_stage(0, 0);
    cp_commit();

    constexpr int NIT = DIM / 64;   // 16
    for (int it = 0; it < NIT; ++it) {
        const int s = it & 1;
        if (it + 1 < NIT) {
            load_stage(s ^ 1, (it + 1) * 64);
            cp_commit();
            cp_wait<1>();
        } else {
            cp_wait<0>();
        }
        __syncthreads();

        const uint32_t sb = sbase + s * STG_BYTES;
#pragma unroll
        for (int ks = 0; ks < 4; ks++) {
            uint32_t ah[2][4], al[2][4], bh[2][4];
#pragma unroll
            for (int mf = 0; mf < 2; mf++) {
                uint32_t off = (a_r + mf * 16) * 128 + ((((ks << 1) | a_k) ^ a_x) << 4);
                ldsm_x4(ah[mf], sb + AH_OFF + off);
                ldsm_x4(al[mf], sb + AL_OFF + off);
            }
#pragma unroll
            for (int nf2 = 0; nf2 < 2; nf2++) {
                uint32_t off = (b_r + nf2 * 16) * 128 + ((((ks << 1) | b_k) ^ b_x) << 4);
                ldsm_x4(bh[nf2], sb + BH_OFF + off);
            }
#pragma unroll
            for (int mf = 0; mf < 2; mf++)
#pragma unroll
                for (int nf = 0; nf < 4; nf++)
                    mma_f16(acc[mf][nf], ah[mf], &bh[nf >> 1][(nf & 1) * 2]);
#pragma unroll
            for (int mf = 0; mf < 2; mf++)
#pragma unroll
                for (int nf = 0; nf < 4; nf++)
                    mma_f16(acc[mf][nf], al[mf], &bh[nf >> 1][(nf & 1) * 2]);
        }
        __syncthreads();
    }

    // epilogue
#pragma unroll
    for (int mf = 0; mf < 2; mf++) {
        const int row0 = bm + wm * 32 + mf * 16 + (lane >> 2);
#pragma unroll
        for (int nf = 0; nf < 4; nf++) {
            const int col = bn + wn * 32 + nf * 8 + (lane & 3) * 2;
            if (MODE == 0) {
                const int h = col >> 6, d = col & 63;
#pragma unroll
                for (int half = 0; half < 2; half++) {
                    const int row = row0 + half * 8;
                    const int b = row >> 11, t = row & 2047;
                    const size_t dst = (((size_t)(b * NHEADS + h) * SEQ) + t) * HDIM + d;
                    float f0 = acc[mf][nf][half * 2 + 0] * scale;
                    float f1 = acc[mf][nf][half * 2 + 1] * scale;
                    if (Clo) {
                        unsigned short h0, l0, h1, l1;
                        split1h(f0, h0, l0);
                        split1h(f1, h1, l1);
                        *(ushort2*)(Chi + dst) = make_ushort2(h0, h1);
                        *(ushort2*)(Clo + dst) = make_ushort2(l0, l1);
                    } else {
                        __half2 p = __floats2half2_rn(f0, f1);
                        *(uint32_t*)(Chi + dst) = *reinterpret_cast<uint32_t*>(&p);
                    }
                }
            } else {
                float b0 = bias[col], b1 = bias[col + 1];
                float2 v0 = make_float2(acc[mf][nf][0] + b0, acc[mf][nf][1] + b1);
                float2 v1 = make_float2(acc[mf][nf][2] + b0, acc[mf][nf][3] + b1);
                *(float2*)(C + (size_t)row0 * DIM + col)       = v0;
                *(float2*)(C + (size_t)(row0 + 8) * DIM + col) = v1;
            }
        }
    }
}

__global__ void __launch_bounds__(256, 2) gemm_qkv_f16()
{
    const int z = blockIdx.z;
    unsigned short* Chi = (z == 0) ? g_q_hi : (z == 1) ? g_k_hi : g_v_hi;
    unsigned short* Clo = (z == 0) ? g_q_lo : nullptr;
    const float scale = (z == 0) ? 0.125f : 1.0f;
    gemm_f16_body<0>(g_x_hi, g_x_lo,
                     g_w_hi + (size_t)z * DIM * DIM,
                     scale, Chi, Clo, nullptr, nullptr);
}

__global__ void __launch_bounds__(256, 2) gemm_out_f16(
    const float* __restrict__ bo, float* __restrict__ out)
{
    gemm_f16_body<1>(g_o_hi, g_o_lo,
                     g_w_hi + (size_t)3 * DIM * DIM,
                     1.0f, nullptr, nullptr, bo, out);
}

// ============================================================================
// Tensor-core flash attention, fp16 2-term (causal) — exact R13.
// ============================================================================
#define ATT_QH 0
#define ATT_QL 8192
#define ATT_STG0 16384
#define ATT_STG_BYTES 16384       // KH 8K | VH 8K
#define ATT_KH 0
#define ATT_VH 8192
#define ATT_NSTG 3
#define ATT_SMEM (ATT_STG0 + ATT_NSTG * ATT_STG_BYTES)   // 65536

#define NEG_INF __int_as_float(0xff800000)

__global__ void __launch_bounds__(128, 1) attn_mma_kernel()
{
    extern __shared__ char dsm[];
    const uint32_t sbase = (uint32_t)__cvta_generic_to_shared(dsm);

    const int tid  = threadIdx.x;
    const int lane = tid & 31;
    const int w    = tid >> 5;
    const int qb   = (gridDim.x - 1) - blockIdx.x;
    const int h    = blockIdx.y;
    const int b    = blockIdx.z;
    const int q0   = qb * 64;

    const size_t head = (size_t)(b * NHEADS + h) * SEQ * HDIM;
    const unsigned short* Qh = g_q_hi + head;
    const unsigned short* Ql = g_q_lo + head;
    const unsigned short* Kh = g_k_hi + head;
    const unsigned short* Vh = g_v_hi + head;

#pragma unroll
    for (int t = 0; t < 4; t++) {
        int c = tid + t * 128;
        int row = c >> 3, ch = c & 7;
        size_t   g = (size_t)(q0 + row) * HDIM + ch * 8;
        uint32_t sofs = row * 128 + ((ch ^ (row & 7)) << 4);
        cp16(sbase + ATT_QH + sofs, Qh + g);
        cp16(sbase + ATT_QL + sofs, Ql + g);
    }

    auto load_kv = [&](int s, int k0) {
        const uint32_t st = sbase + ATT_STG0 + s * ATT_STG_BYTES;
#pragma unroll
        for (int t = 0; t < 4; t++) {
            int c = tid + t * 128;
            int row = c >> 3, ch = c & 7;
            size_t   g = (size_t)(k0 + row) * HDIM + ch * 8;
            uint32_t sofs = row * 128 + ((ch ^ (row & 7)) << 4);
            cp16(st + ATT_KH + sofs, Kh + g);
            cp16(st + ATT_VH + sofs, Vh + g);
        }
    };

    const int kmax = qb;

    load_kv(0, 0);
    cp_commit();
    if (kmax >= 1) {
        load_kv(1, 64);
        cp_commit();
    }

    const int a_r = w * 16 + (lane & 15);
    const int a_k = lane >> 4;
    const int a_x = a_r & 7;
    const int k_r = (lane & 7) + ((lane >> 4) << 3);
    const int k_k = (lane >> 3) & 1;
    const int v_r = (lane & 7) + (((lane >> 3) & 1) << 3);
    const int v_c = lane >> 4;

    uint32_t qh[4][4], ql[4][4];

    float m_run[2] = {NEG_INF, NEG_INF};
    float l_run[2] = {0.0f, 0.0f};
    float acc_o[8][4];
#pragma unroll
    for (int i = 0; i < 8; i++)
#pragma unroll
        for (int j = 0; j < 4; j++) acc_o[i][j] = 0.0f;

    int s = 0;
    for (int kb = 0; kb <= kmax; kb++) {
        const int k0 = kb * 64;
        if (kb + 2 <= kmax) {
            load_kv((s + 2) % ATT_NSTG, (kb + 2) * 64);
            cp_commit();
            cp_wait<2>();
        } else if (kb + 1 <= kmax) {
            cp_wait<1>();
        } else {
            cp_wait<0>();
        }
        __syncthreads();

        if (kb == 0) {
#pragma unroll
            for (int ks = 0; ks < 4; ks++) {
                uint32_t off = a_r * 128 + ((((ks << 1) | a_k) ^ a_x) << 4);
                ldsm_x4(qh[ks], sbase + ATT_QH + off);
                ldsm_x4(ql[ks], sbase + ATT_QL + off);
            }
        }

        const uint32_t st = sbase + ATT_STG0 + s * ATT_STG_BYTES;

        float s_acc[8][4];
#pragma unroll
        for (int i = 0; i < 8; i++)
#pragma unroll
            for (int j = 0; j < 4; j++) s_acc[i][j] = 0.0f;

#pragma unroll
        for (int ks = 0; ks < 4; ks++) {
            uint32_t bh[4][4];
#pragma unroll
            for (int nf2 = 0; nf2 < 4; nf2++) {
                int r = k_r + nf2 * 16;
                uint32_t off = r * 128 + ((((ks << 1) | k_k) ^ (r & 7)) << 4);
                ldsm_x4(bh[nf2], st + ATT_KH + off);
            }
#pragma unroll
            for (int nf = 0; nf < 8; nf++)
                mma_f16(s_acc[nf], qh[ks], &bh[nf >> 1][(nf & 1) * 2]);
#pragma unroll
            for (int nf = 0; nf < 8; nf++)
                mma_f16(s_acc[nf], ql[ks], &bh[nf >> 1][(nf & 1) * 2]);
        }

        if (kb == qb) {
            const int qpos0 = q0 + w * 16 + (lane >> 2);
            const int kbase = k0 + (lane & 3) * 2;
#pragma unroll
            for (int nf = 0; nf < 8; nf++) {
                const int kp = kbase + nf * 8;
                if (kp     > qpos0)     s_acc[nf][0] = NEG_INF;
                if (kp + 1 > qpos0)     s_acc[nf][1] = NEG_INF;
                if (kp     > qpos0 + 8) s_acc[nf][2] = NEG_INF;
                if (kp + 1 > qpos0 + 8) s_acc[nf][3] = NEG_INF;
            }
        }

#pragma unroll
        for (int half = 0; half < 2; half++) {
            float mx = NEG_INF;
#pragma unroll
            for (int nf = 0; nf < 8; nf++)
                mx = fmaxf(mx, fmaxf(s_acc[nf][half * 2], s_acc[nf][half * 2 + 1]));
            mx = fmaxf(mx, __shfl_xor_sync(0xffffffffu, mx, 1));
            mx = fmaxf(mx, __shfl_xor_sync(0xffffffffu, mx, 2));

            const float mnew  = fmaxf(m_run[half], mx);
            const float alpha = __expf(m_run[half] - mnew);
            m_run[half] = mnew;

            float sum = 0.0f;
#pragma unroll
            for (int nf = 0; nf < 8; nf++) {
                float p0 = __expf(s_acc[nf][half * 2]     - mnew);
                float p1 = __expf(s_acc[nf][half * 2 + 1] - mnew);
                s_acc[nf][half * 2]     = p0;
                s_acc[nf][half * 2 + 1] = p1;
                sum += p0 + p1;
            }
            sum += __shfl_xor_sync(0xffffffffu, sum, 1);
            sum += __shfl_xor_sync(0xffffffffu, sum, 2);
            l_run[half] = l_run[half] * alpha + sum;

#pragma unroll
            for (int dn = 0; dn < 8; dn++) {
                acc_o[dn][half * 2]     *= alpha;
                acc_o[dn][half * 2 + 1] *= alpha;
            }
        }

#pragma unroll
        for (int kc = 0; kc < 4; kc++) {
            uint32_t ah[4], al[4];
#pragma unroll
            for (int q = 0; q < 2; q++) {
                const float* sc = s_acc[2 * kc + q];
                float h0 = h_hi(sc[0]), h1 = h_hi(sc[1]);
                float h2 = h_hi(sc[2]), h3 = h_hi(sc[3]);
                ah[q * 2 + 0] = h2pack(h0, h1);
                ah[q * 2 + 1] = h2pack(h2, h3);
                al[q * 2 + 0] = h2pack(sc[0] - h0, sc[1] - h1);
                al[q * 2 + 1] = h2pack(sc[2] - h2, sc[3] - h3);
            }
            uint32_t vh[4][4];
#pragma unroll
            for (int dg = 0; dg < 4; dg++) {
                int r = v_r + kc * 16;
                int ch = v_c + dg * 2;
                uint32_t off = r * 128 + ((ch ^ (r & 7)) << 4);
                ldsm_x4_t(vh[dg], st + ATT_VH + off);
            }
#pragma unroll
            for (int dg = 0; dg < 4; dg++)
#pragma unroll
                for (int q = 0; q < 2; q++)
                    mma_f16(acc_o[dg * 2 + q], ah, &vh[dg][q * 2]);
#pragma unroll
            for (int dg = 0; dg < 4; dg++)
#pragma unroll
                for (int q = 0; q < 2; q++)
                    mma_f16(acc_o[dg * 2 + q], al, &vh[dg][q * 2]);
        }
        __syncthreads();
        s = (s + 1) % ATT_NSTG;
    }

    // ---- epilogue: normalize, fp16 split, store token-major ----
    const float inv0 = 1.0f / l_run[0];
    const float inv1 = 1.0f / l_run[1];
    const int row0 = q0 + w * 16 + (lane >> 2);
    const size_t tok0 = (size_t)(b * SEQ + row0) * DIM + h * HDIM;
    const size_t tok1 = tok0 + 8 * DIM;
#pragma unroll
    for (int dn = 0; dn < 8; dn++) {
        const int d = dn * 8 + (lane & 3) * 2;
        float f0 = acc_o[dn][0] * inv0;
        float f1 = acc_o[dn][1] * inv0;
        float f2 = acc_o[dn][2] * inv1;
        float f3 = acc_o[dn][3] * inv1;
        unsigned short h0, l0, h1, l1, h2, l2, h3, l3;
        split1h(f0, h0, l0); split1h(f1, h1, l1);
        split1h(f2, h2, l2); split1h(f3, h3, l3);
        *(ushort2*)(g_o_hi + tok0 + d) = make_ushort2(h0, h1);
        *(ushort2*)(g_o_lo + tok0 + d) = make_ushort2(l0, l1);
        *(ushort2*)(g_o_hi + tok1 + d) = make_ushort2(h2, h3);
        *(ushort2*)(g_o_lo + tok1 + d) = make_ushort2(l2, l3);
    }
}

// ============================================================================
// launch
// ============================================================================
extern "C" void kernel_launch(void* const* d_in, const int* in_sizes, int n_in,
                              void* d_out, int out_size)
{
    const float* x  = (const float*)d_in[0];
    const float* Wq = (const float*)d_in[1];
    const float* Wk = (const float*)d_in[2];
    const float* Wv = (const float*)d_in[3];
    const float* Wo = (const float*)d_in[4];
    const float* bo = (const float*)d_in[5];
    float* out = (float*)d_out;

    cudaFuncSetAttribute(gemm_qkv_f16,   cudaFuncAttributeMaxDynamicSharedMemorySize, GEMM_SMEM);
    cudaFuncSetAttribute(gemm_out_f16,   cudaFuncAttributeMaxDynamicSharedMemorySize, GEMM_SMEM);
    cudaFuncSetAttribute(attn_mma_kernel, cudaFuncAttributeMaxDynamicSharedMemorySize, ATT_SMEM);

    // fused fp16 splits (x hi/lo; W hi only)
    split_all_kernel<<<2048, 256>>>(x, Wq, Wk, Wv, Wo);

    // QKV projections -> Q fp16 hi/lo (pre-scaled), K/V fp16 hi; head-major
    dim3 gridQKV(DIM / 64, MTOT / 128, 3);
    gemm_qkv_f16<<<gridQKV, 256, GEMM_SMEM>>>();

    // fp16 2-term flash attention (BQ=64, 3-stage KV ring)
    dim3 gridAtt(SEQ / 64, NHEADS, BATCH);
    attn_mma_kernel<<<gridAtt, 128, ATT_SMEM>>>();

    // output projection + bias (fp16 2-term)
    dim3 gridOut(DIM / 64, MTOT / 128);
    gemm_out_f16<<<gridOut, 256, GEMM_SMEM>>>(bo, out);
}

// round 15
// speedup vs baseline: 1.8305x; 1.3239x over previous
#include <cuda_runtime.h>
#include <cuda_fp16.h>
#include <math.h>
#include <stdint.h>

#define DIM    1024
#define NHEADS 16
#define HDIM   64
#define BATCH  2
#define SEQ    2048
#define MTOT   (BATCH * SEQ)   // 4096

// ---------------- scratch (static device globals; no allocation) ----------------
__device__ unsigned short g_x_hi[MTOT * DIM];          // x fp16 (hi only)
__device__ unsigned short g_w_hi[4 * DIM * DIM];       // Wq,Wk,Wv,Wo fp16 (hi only)
// Q hi/lo fp16; K/V fp16 hi only. Head-major [B][H][T][D].
__device__ unsigned short g_q_hi[MTOT * DIM];
__device__ unsigned short g_q_lo[MTOT * DIM];
__device__ unsigned short g_k_hi[MTOT * DIM];
__device__ unsigned short g_v_hi[MTOT * DIM];
// attention output, token-major [MTOT][DIM], fp16 hi only
__device__ unsigned short g_o_hi[MTOT * DIM];

// ============================================================================
// helpers (fp16)
// ============================================================================
__device__ __forceinline__ void split1h(float v, unsigned short& h, unsigned short& l)
{
    __half hh = __float2half_rn(v);
    h = __half_as_ushort(hh);
    l = __half_as_ushort(__float2half_rn(v - __half2float(hh)));
}
__device__ __forceinline__ uint32_t h2pack(float a, float b)
{
    __half2 t = __floats2half2_rn(a, b);
    return *reinterpret_cast<uint32_t*>(&t);
}
__device__ __forceinline__ float h_hi(float v)
{
    return __half2float(__float2half_rn(v));
}

// fused split: x -> fp16 (1024 blocks), W -> fp16 (1024 blocks); 4 float4/thread.
__global__ void split_all_kernel(const float* __restrict__ x,
                                 const float* __restrict__ Wq,
                                 const float* __restrict__ Wk,
                                 const float* __restrict__ Wv,
                                 const float* __restrict__ Wo)
{
    const int blk = blockIdx.x;
    if (blk < 1024) {
        int base = blk * 1024 + threadIdx.x;
#pragma unroll
        for (int j = 0; j < 4; j++) {
            int i = base + j * 256;
            float4 v = ((const float4*)x)[i];
            __half2 p0 = __floats2half2_rn(v.x, v.y);
            __half2 p1 = __floats2half2_rn(v.z, v.w);
            ((uint2*)g_x_hi)[i] = make_uint2(*reinterpret_cast<uint32_t*>(&p0),
                                             *reinterpret_cast<uint32_t*>(&p1));
        }
    } else {
        int wbase = (blk - 1024) * 1024 + threadIdx.x;
#pragma unroll
        for (int j = 0; j < 4; j++) {
            int widx = wbase + j * 256;
            int z = widx >> 18;
            int i = widx & 262143;
            const float* w = (z == 0) ? Wq : (z == 1) ? Wk : (z == 2) ? Wv : Wo;
            float4 v = ((const float4*)w)[i];
            __half2 p0 = __floats2half2_rn(v.x, v.y);
            __half2 p1 = __floats2half2_rn(v.z, v.w);
            ((uint2*)g_w_hi)[(size_t)z * 262144 + i] =
                make_uint2(*reinterpret_cast<uint32_t*>(&p0),
                           *reinterpret_cast<uint32_t*>(&p1));
        }
    }
}

// ============================================================================
// async / mma primitives
// ============================================================================
__device__ __forceinline__ void cp16(uint32_t dst, const void* src)
{
    asm volatile("cp.async.cg.shared.global [%0], [%1], 16;\n" :: "r"(dst), "l"(src));
}
__device__ __forceinline__ void cp_commit()
{
    asm volatile("cp.async.commit_group;\n");
}
template<int N> __device__ __forceinline__ void cp_wait()
{
    asm volatile("cp.async.wait_group %0;\n" :: "n"(N));
}
__device__ __forceinline__ void ldsm_x4(uint32_t* r, uint32_t addr)
{
    asm volatile("ldmatrix.sync.aligned.m8n8.x4.shared.b16 {%0,%1,%2,%3}, [%4];"
                 : "=r"(r[0]), "=r"(r[1]), "=r"(r[2]), "=r"(r[3]) : "r"(addr));
}
__device__ __forceinline__ void ldsm_x4_t(uint32_t* r, uint32_t addr)
{
    asm volatile("ldmatrix.sync.aligned.m8n8.x4.trans.shared.b16 {%0,%1,%2,%3}, [%4];"
                 : "=r"(r[0]), "=r"(r[1]), "=r"(r[2]), "=r"(r[3]) : "r"(addr));
}
__device__ __forceinline__ void mma_f16(float* c, const uint32_t* a, const uint32_t* b)
{
    asm volatile("mma.sync.aligned.m16n8k16.row.col.f32.f16.f16.f32 "
                 "{%0,%1,%2,%3},{%4,%5,%6,%7},{%8,%9},{%0,%1,%2,%3};"
                 : "+f"(c[0]), "+f"(c[1]), "+f"(c[2]), "+f"(c[3])
                 : "r"(a[0]), "r"(a[1]), "r"(a[2]), "r"(a[3]), "r"(b[0]), "r"(b[1]));
}

// ============================================================================
// pure fp16 GEMM:  C = A*B^T (fp32 accum).
// BM=128, BN=64, BK=128 (256B smem rows, two-atom swizzle), 256 threads
// (8 warps: 4m x 2n), 2-stage cp.async, 2 CTAs/SM (96KB smem/CTA).
// 64 MMAs per warp between barriers, 8 K-chunks.
// MODE 0: Q -> fp16 hi/lo (Clo!=null), K/V -> fp16 hi (Clo==null); head-major.
// MODE 1: fp32 + bias.
// ============================================================================
#define STG_BYTES 49152       // AH 32768 | BH 16384
#define AH_OFF 0
#define BH_OFF 32768
#define GEMM_SMEM (2 * STG_BYTES)   // 98304

template<int MODE>
__device__ __forceinline__ void gemm_f16_body(
    const unsigned short* __restrict__ Ah,
    const unsigned short* __restrict__ Bh,
    float scale,
    unsigned short* __restrict__ Chi, unsigned short* __restrict__ Clo,
    const float* __restrict__ bias, float* __restrict__ C)
{
    extern __shared__ char dsm[];
    const uint32_t sbase = (uint32_t)__cvta_generic_to_shared(dsm);

    const int tid  = threadIdx.x;
    const int bm   = blockIdx.y * 128;
    const int bn   = blockIdx.x * 64;
    const int lane = tid & 31;
    const int warp = tid >> 5;
    const int wm   = warp & 3;
    const int wn   = warp >> 2;

    // 256B rows: chunk ch in 0..15; swizzled chunk = ((ch&7)^(row&7)) | (ch&8)
    auto load_stage = [&](int s, int k0) {
        const uint32_t sb = sbase + s * STG_BYTES;
#pragma unroll
        for (int t = 0; t < 8; t++) {
            int c   = tid + t * 256;        // 0..2047
            int row = c >> 4, ch = c & 15;
            size_t   gofs = (size_t)(bm + row) * DIM + k0 + ch * 8;
            uint32_t sw   = ((uint32_t)(((ch & 7) ^ (row & 7)) | (ch & 8))) << 4;
            cp16(sb + AH_OFF + row * 256 + sw, Ah + gofs);
        }
#pragma unroll
        for (int t = 0; t < 4; t++) {
            int c   = tid + t * 256;        // 0..1023
            int row = c >> 4, ch = c & 15;
            size_t   gofs = (size_t)(bn + row) * DIM + k0 + ch * 8;
            uint32_t sw   = ((uint32_t)(((ch & 7) ^ (row & 7)) | (ch & 8))) << 4;
            cp16(sb + BH_OFF + row * 256 + sw, Bh + gofs);
        }
    };

    float acc[2][4][4];
#pragma unroll
    for (int i = 0; i < 2; i++)
#pragma unroll
        for (int j = 0; j < 4; j++)
#pragma unroll
            for (int k = 0; k < 4; k++) acc[i][j][k] = 0.0f;

    const int a_r = wm * 32 + (lane & 15);
    const int a_k = (lane >> 4);
    const int a_x = a_r & 7;
    const int b_r = wn * 32 + (lane & 7) + ((lane >> 4) << 3);
    const int b_k = (lane >> 3) & 1;
    const int b_x = b_r & 7;

    load_stage(0, 0);
    cp_commit();

    constexpr int NIT = DIM / 128;   // 8
    for (int it = 0; it < NIT; ++it) {
        const int s = it & 1;
        if (it + 1 < NIT) {
            load_stage(s ^ 1, (it + 1) * 128);
            cp_commit();
            cp_wait<1>();
        } else {
            cp_wait<0>();
        }
        __syncthreads();

        const uint32_t sb = sbase + s * STG_BYTES;
#pragma unroll
        for (int ks = 0; ks < 8; ks++) {
            uint32_t ah[2][4], bh[2][4];
            const int cha = (ks << 1) | a_k;     // 0..15
            const int chb = (ks << 1) | b_k;
#pragma unroll
            for (int mf = 0; mf < 2; mf++) {
                uint32_t sw = ((uint32_t)((((cha & 7) ^ a_x)) | (cha & 8))) << 4;
                ldsm_x4(ah[mf], sb + AH_OFF + (a_r + mf * 16) * 256 + sw);
            }
#pragma unroll
            for (int nf2 = 0; nf2 < 2; nf2++) {
                uint32_t sw = ((uint32_t)((((chb & 7) ^ b_x)) | (chb & 8))) << 4;
                ldsm_x4(bh[nf2], sb + BH_OFF + (b_r + nf2 * 16) * 256 + sw);
            }
#pragma unroll
            for (int mf = 0; mf < 2; mf++)
#pragma unroll
                for (int nf = 0; nf < 4; nf++)
                    mma_f16(acc[mf][nf], ah[mf], &bh[nf >> 1][(nf & 1) * 2]);
        }
        __syncthreads();
    }

    // epilogue
#pragma unroll
    for (int mf = 0; mf < 2; mf++) {
        const int row0 = bm + wm * 32 + mf * 16 + (lane >> 2);
#pragma unroll
        for (int nf = 0; nf < 4; nf++) {
            const int col = bn + wn * 32 + nf * 8 + (lane & 3) * 2;
            if (MODE == 0) {
                const int h = col >> 6, d = col & 63;
#pragma unroll
                for (int half = 0; half < 2; half++) {
                    const int row = row0 + half * 8;
                    const int b = row >> 11, t = row & 2047;
                    const size_t dst = (((size_t)(b * NHEADS + h) * SEQ) + t) * HDIM + d;
                    float f0 = acc[mf][nf][half * 2 + 0] * scale;
                    float f1 = acc[mf][nf][half * 2 + 1] * scale;
                    if (Clo) {
                        unsigned short h0, l0, h1, l1;
                        split1h(f0, h0, l0);
                        split1h(f1, h1, l1);
                        *(ushort2*)(Chi + dst) = make_ushort2(h0, h1);
                        *(ushort2*)(Clo + dst) = make_ushort2(l0, l1);
                    } else {
                        __half2 p = __floats2half2_rn(f0, f1);
                        *(uint32_t*)(Chi + dst) = *reinterpret_cast<uint32_t*>(&p);
                    }
                }
            } else {
                float b0 = bias[col], b1 = bias[col + 1];
                float2 v0 = make_float2(acc[mf][nf][0] + b0, acc[mf][nf][1] + b1);
                float2 v1 = make_float2(acc[mf][nf][2] + b0, acc[mf][nf][3] + b1);
                *(float2*)(C + (size_t)row0 * DIM + col)       = v0;
                *(float2*)(C + (size_t)(row0 + 8) * DIM + col) = v1;
            }
        }
    }
}

__global__ void __launch_bounds__(256, 2) gemm_qkv_f16()
{
    const int z = blockIdx.z;
    unsigned short* Chi = (z == 0) ? g_q_hi : (z == 1) ? g_k_hi : g_v_hi;
    unsigned short* Clo = (z == 0) ? g_q_lo : nullptr;
    const float scale = (z == 0) ? 0.125f : 1.0f;
    gemm_f16_body<0>(g_x_hi, g_w_hi + (size_t)z * DIM * DIM,
                     scale, Chi, Clo, nullptr, nullptr);
}

__global__ void __launch_bounds__(256, 2) gemm_out_f16(
    const float* __restrict__ bo, float* __restrict__ out)
{
    gemm_f16_body<1>(g_o_hi, g_w_hi + (size_t)3 * DIM * DIM,
                     1.0f, nullptr, nullptr, bo, out);
}

// ============================================================================
// Tensor-core flash attention, fp16 2-term (causal) — R13/R14 math.
// BQ=64: 128 threads (4 warps), BK=64, 3-stage KV ring, 64KB smem.
// Epilogue stores fp16 hi only (out-proj is 1-term now).
// ============================================================================
#define ATT_QH 0
#define ATT_QL 8192
#define ATT_STG0 16384
#define ATT_STG_BYTES 16384       // KH 8K | VH 8K
#define ATT_KH 0
#define ATT_VH 8192
#define ATT_NSTG 3
#define ATT_SMEM (ATT_STG0 + ATT_NSTG * ATT_STG_BYTES)   // 65536

#define NEG_INF __int_as_float(0xff800000)

__global__ void __launch_bounds__(128, 1) attn_mma_kernel()
{
    extern __shared__ char dsm[];
    const uint32_t sbase = (uint32_t)__cvta_generic_to_shared(dsm);

    const int tid  = threadIdx.x;
    const int lane = tid & 31;
    const int w    = tid >> 5;
    const int qb   = (gridDim.x - 1) - blockIdx.x;
    const int h    = blockIdx.y;
    const int b    = blockIdx.z;
    const int q0   = qb * 64;

    const size_t head = (size_t)(b * NHEADS + h) * SEQ * HDIM;
    const unsigned short* Qh = g_q_hi + head;
    const unsigned short* Ql = g_q_lo + head;
    const unsigned short* Kh = g_k_hi + head;
    const unsigned short* Vh = g_v_hi + head;

#pragma unroll
    for (int t = 0; t < 4; t++) {
        int c = tid + t * 128;
        int row = c >> 3, ch = c & 7;
        size_t   g = (size_t)(q0 + row) * HDIM + ch * 8;
        uint32_t sofs = row * 128 + ((ch ^ (row & 7)) << 4);
        cp16(sbase + ATT_QH + sofs, Qh + g);
        cp16(sbase + ATT_QL + sofs, Ql + g);
    }

    auto load_kv = [&](int s, int k0) {
        const uint32_t st = sbase + ATT_STG0 + s * ATT_STG_BYTES;
#pragma unroll
        for (int t = 0; t < 4; t++) {
            int c = tid + t * 128;
            int row = c >> 3, ch = c & 7;
            size_t   g = (size_t)(k0 + row) * HDIM + ch * 8;
            uint32_t sofs = row * 128 + ((ch ^ (row & 7)) << 4);
            cp16(st + ATT_KH + sofs, Kh + g);
            cp16(st + ATT_VH + sofs, Vh + g);
        }
    };

    const int kmax = qb;

    load_kv(0, 0);
    cp_commit();
    if (kmax >= 1) {
        load_kv(1, 64);
        cp_commit();
    }

    const int a_r = w * 16 + (lane & 15);
    const int a_k = lane >> 4;
    const int a_x = a_r & 7;
    const int k_r = (lane & 7) + ((lane >> 4) << 3);
    const int k_k = (lane >> 3) & 1;
    const int v_r = (lane & 7) + (((lane >> 3) & 1) << 3);
    const int v_c = lane >> 4;

    uint32_t qh[4][4], ql[4][4];

    float m_run[2] = {NEG_INF, NEG_INF};
    float l_run[2] = {0.0f, 0.0f};
    float acc_o[8][4];
#pragma unroll
    for (int i = 0; i < 8; i++)
#pragma unroll
        for (int j = 0; j < 4; j++) acc_o[i][j] = 0.0f;

    int s = 0;
    for (int kb = 0; kb <= kmax; kb++) {
        const int k0 = kb * 64;
        if (kb + 2 <= kmax) {
            load_kv((s + 2) % ATT_NSTG, (kb + 2) * 64);
            cp_commit();
            cp_wait<2>();
        } else if (kb + 1 <= kmax) {
            cp_wait<1>();
        } else {
            cp_wait<0>();
        }
        __syncthreads();

        if (kb == 0) {
#pragma unroll
            for (int ks = 0; ks < 4; ks++) {
                uint32_t off = a_r * 128 + ((((ks << 1) | a_k) ^ a_x) << 4);
                ldsm_x4(qh[ks], sbase + ATT_QH + off);
                ldsm_x4(ql[ks], sbase + ATT_QL + off);
            }
        }

        const uint32_t st = sbase + ATT_STG0 + s * ATT_STG_BYTES;

        float s_acc[8][4];
#pragma unroll
        for (int i = 0; i < 8; i++)
#pragma unroll
            for (int j = 0; j < 4; j++) s_acc[i][j] = 0.0f;

#pragma unroll
        for (int ks = 0; ks < 4; ks++) {
            uint32_t bh[4][4];
#pragma unroll
            for (int nf2 = 0; nf2 < 4; nf2++) {
                int r = k_r + nf2 * 16;
                uint32_t off = r * 128 + ((((ks << 1) | k_k) ^ (r & 7)) << 4);
                ldsm_x4(bh[nf2], st + ATT_KH + off);
            }
#pragma unroll
            for (int nf = 0; nf < 8; nf++)
                mma_f16(s_acc[nf], qh[ks], &bh[nf >> 1][(nf & 1) * 2]);
#pragma unroll
            for (int nf = 0; nf < 8; nf++)
                mma_f16(s_acc[nf], ql[ks], &bh[nf >> 1][(nf & 1) * 2]);
        }

        if (kb == qb) {
            const int qpos0 = q0 + w * 16 + (lane >> 2);
            const int kbase = k0 + (lane & 3) * 2;
#pragma unroll
            for (int nf = 0; nf < 8; nf++) {
                const int kp = kbase + nf * 8;
                if (kp     > qpos0)     s_acc[nf][0] = NEG_INF;
                if (kp + 1 > qpos0)     s_acc[nf][1] = NEG_INF;
                if (kp     > qpos0 + 8) s_acc[nf][2] = NEG_INF;
                if (kp + 1 > qpos0 + 8) s_acc[nf][3] = NEG_INF;
            }
        }

#pragma unroll
        for (int half = 0; half < 2; half++) {
            float mx = NEG_INF;
#pragma unroll
            for (int nf = 0; nf < 8; nf++)
                mx = fmaxf(mx, fmaxf(s_acc[nf][half * 2], s_acc[nf][half * 2 + 1]));
            mx = fmaxf(mx, __shfl_xor_sync(0xffffffffu, mx, 1));
            mx = fmaxf(mx, __shfl_xor_sync(0xffffffffu, mx, 2));

            const float mnew  = fmaxf(m_run[half], mx);
            const float alpha = __expf(m_run[half] - mnew);
            m_run[half] = mnew;

            float sum = 0.0f;
#pragma unroll
            for (int nf = 0; nf < 8; nf++) {
                float p0 = __expf(s_acc[nf][half * 2]     - mnew);
                float p1 = __expf(s_acc[nf][half * 2 + 1] - mnew);
                s_acc[nf][half * 2]     = p0;
                s_acc[nf][half * 2 + 1] = p1;
                sum += p0 + p1;
            }
            sum += __shfl_xor_sync(0xffffffffu, sum, 1);
            sum += __shfl_xor_sync(0xffffffffu, sum, 2);
            l_run[half] = l_run[half] * alpha + sum;

#pragma unroll
            for (int dn = 0; dn < 8; dn++) {
                acc_o[dn][half * 2]     *= alpha;
                acc_o[dn][half * 2 + 1] *= alpha;
            }
        }

#pragma unroll
        for (int kc = 0; kc < 4; kc++) {
            uint32_t ah[4], al[4];
#pragma unroll
            for (int q = 0; q < 2; q++) {
                const float* sc = s_acc[2 * kc + q];
                float h0 = h_hi(sc[0]), h1 = h_hi(sc[1]);
                float h2 = h_hi(sc[2]), h3 = h_hi(sc[3]);
                ah[q * 2 + 0] = h2pack(h0, h1);
                ah[q * 2 + 1] = h2pack(h2, h3);
                al[q * 2 + 0] = h2pack(sc[0] - h0, sc[1] - h1);
                al[q * 2 + 1] = h2pack(sc[2] - h2, sc[3] - h3);
            }
            uint32_t vh[4][4];
#pragma unroll
            for (int dg = 0; dg < 4; dg++) {
                int r = v_r + kc * 16;
                int ch = v_c + dg * 2;
                uint32_t off = r * 128 + ((ch ^ (r & 7)) << 4);
                ldsm_x4_t(vh[dg], st + ATT_VH + off);
            }
#pragma unroll
            for (int dg = 0; dg < 4; dg++)
#pragma unroll
                for (int q = 0; q < 2; q++)
                    mma_f16(acc_o[dg * 2 + q], ah, &vh[dg][q * 2]);
#pragma unroll
            for (int dg = 0; dg < 4; dg++)
#pragma unroll
                for (int q = 0; q < 2; q++)
                    mma_f16(acc_o[dg * 2 + q], al, &vh[dg][q * 2]);
        }
        __syncthreads();
        s = (s + 1) % ATT_NSTG;
    }

    // ---- epilogue: normalize, store fp16 hi, token-major ----
    const float inv0 = 1.0f / l_run[0];
    const float inv1 = 1.0f / l_run[1];
    const int row0 = q0 + w * 16 + (lane >> 2);
    const size_t tok0 = (size_t)(b * SEQ + row0) * DIM + h * HDIM;
    const size_t tok1 = tok0 + 8 * DIM;
#pragma unroll
    for (int dn = 0; dn < 8; dn++) {
        const int d = dn * 8 + (lane & 3) * 2;
        __half2 p0 = __floats2half2_rn(acc_o[dn][0] * inv0, acc_o[dn][1] * inv0);
        __half2 p1 = __floats2half2_rn(acc_o[dn][2] * inv1, acc_o[dn][3] * inv1);
        *(uint32_t*)(g_o_hi + tok0 + d) = *reinterpret_cast<uint32_t*>(&p0);
        *(uint32_t*)(g_o_hi + tok1 + d) = *reinterpret_cast<uint32_t*>(&p1);
    }
}

// ============================================================================
// launch
// ============================================================================
extern "C" void kernel_launch(void* const* d_in, const int* in_sizes, int n_in,
                              void* d_out, int out_size)
{
    const float* x  = (const float*)d_in[0];
    const float* Wq = (const float*)d_in[1];
    const float* Wk = (const float*)d_in[2];
    const float* Wv = (const float*)d_in[3];
    const float* Wo = (const float*)d_in[4];
    const float* bo = (const float*)d_in[5];
    float* out = (float*)d_out;

    cudaFuncSetAttribute(gemm_qkv_f16,    cudaFuncAttributeMaxDynamicSharedMemorySize, GEMM_SMEM);
    cudaFuncSetAttribute(gemm_out_f16,    cudaFuncAttributeMaxDynamicSharedMemorySize, GEMM_SMEM);
    cudaFuncSetAttribute(attn_mma_kernel, cudaFuncAttributeMaxDynamicSharedMemorySize, ATT_SMEM);

    // fused fp16 conversions (x and W, hi only)
    split_all_kernel<<<2048, 256>>>(x, Wq, Wk, Wv, Wo);

    // QKV projections (1-term fp16) -> Q fp16 hi/lo (pre-scaled), K/V fp16 hi
    dim3 gridQKV(DIM / 64, MTOT / 128, 3);
    gemm_qkv_f16<<<gridQKV, 256, GEMM_SMEM>>>();

    // fp16 2-term flash attention (BQ=64, 3-stage KV ring)
    dim3 gridAtt(SEQ / 64, NHEADS, BATCH);
    attn_mma_kernel<<<gridAtt, 128, ATT_SMEM>>>();

    // output projection + bias (1-term fp16)
    dim3 gridOut(DIM / 64, MTOT / 128);
    gemm_out_f16<<<gridOut, 256, GEMM_SMEM>>>(bo, out);
}

// round 16
// speedup vs baseline: 2.0374x; 1.1131x over previous
#include <cuda_runtime.h>
#include <cuda_fp16.h>
#include <math.h>
#include <stdint.h>

#define DIM    1024
#define NHEADS 16
#define HDIM   64
#define BATCH  2
#define SEQ    2048
#define MTOT   (BATCH * SEQ)   // 4096

// ---------------- scratch (static device globals; no allocation) ----------------
__device__ unsigned short g_x_hi[MTOT * DIM];          // x fp16
__device__ unsigned short g_w_hi[4 * DIM * DIM];       // Wq,Wk,Wv,Wo fp16
// Q hi/lo fp16; K/V fp16 hi only. Head-major [B][H][T][D].
__device__ unsigned short g_q_hi[MTOT * DIM];
__device__ unsigned short g_q_lo[MTOT * DIM];
__device__ unsigned short g_k_hi[MTOT * DIM];
__device__ unsigned short g_v_hi[MTOT * DIM];
// attention output, token-major [MTOT][DIM], fp16
__device__ unsigned short g_o_hi[MTOT * DIM];

// ============================================================================
// helpers (fp16)
// ============================================================================
__device__ __forceinline__ void split1h(float v, unsigned short& h, unsigned short& l)
{
    __half hh = __float2half_rn(v);
    h = __half_as_ushort(hh);
    l = __half_as_ushort(__float2half_rn(v - __half2float(hh)));
}
__device__ __forceinline__ uint32_t h2pack(float a, float b)
{
    __half2 t = __floats2half2_rn(a, b);
    return *reinterpret_cast<uint32_t*>(&t);
}
__device__ __forceinline__ float h_hi(float v)
{
    return __half2float(__float2half_rn(v));
}

// fused convert: x -> fp16 (1024 blocks), W -> fp16 (1024 blocks); 4 float4/thread.
__global__ void split_all_kernel(const float* __restrict__ x,
                                 const float* __restrict__ Wq,
                                 const float* __restrict__ Wk,
                                 const float* __restrict__ Wv,
                                 const float* __restrict__ Wo)
{
    const int blk = blockIdx.x;
    if (blk < 1024) {
        int base = blk * 1024 + threadIdx.x;
#pragma unroll
        for (int j = 0; j < 4; j++) {
            int i = base + j * 256;
            float4 v = ((const float4*)x)[i];
            __half2 p0 = __floats2half2_rn(v.x, v.y);
            __half2 p1 = __floats2half2_rn(v.z, v.w);
            ((uint2*)g_x_hi)[i] = make_uint2(*reinterpret_cast<uint32_t*>(&p0),
                                             *reinterpret_cast<uint32_t*>(&p1));
        }
    } else {
        int wbase = (blk - 1024) * 1024 + threadIdx.x;
#pragma unroll
        for (int j = 0; j < 4; j++) {
            int widx = wbase + j * 256;
            int z = widx >> 18;
            int i = widx & 262143;
            const float* w = (z == 0) ? Wq : (z == 1) ? Wk : (z == 2) ? Wv : Wo;
            float4 v = ((const float4*)w)[i];
            __half2 p0 = __floats2half2_rn(v.x, v.y);
            __half2 p1 = __floats2half2_rn(v.z, v.w);
            ((uint2*)g_w_hi)[(size_t)z * 262144 + i] =
                make_uint2(*reinterpret_cast<uint32_t*>(&p0),
                           *reinterpret_cast<uint32_t*>(&p1));
        }
    }
}

// ============================================================================
// async / mma primitives
// ============================================================================
__device__ __forceinline__ void cp16(uint32_t dst, const void* src)
{
    asm volatile("cp.async.cg.shared.global [%0], [%1], 16;\n" :: "r"(dst), "l"(src));
}
__device__ __forceinline__ void cp_commit()
{
    asm volatile("cp.async.commit_group;\n");
}
template<int N> __device__ __forceinline__ void cp_wait()
{
    asm volatile("cp.async.wait_group %0;\n" :: "n"(N));
}
__device__ __forceinline__ void ldsm_x4(uint32_t* r, uint32_t addr)
{
    asm volatile("ldmatrix.sync.aligned.m8n8.x4.shared.b16 {%0,%1,%2,%3}, [%4];"
                 : "=r"(r[0]), "=r"(r[1]), "=r"(r[2]), "=r"(r[3]) : "r"(addr));
}
__device__ __forceinline__ void ldsm_x4_t(uint32_t* r, uint32_t addr)
{
    asm volatile("ldmatrix.sync.aligned.m8n8.x4.trans.shared.b16 {%0,%1,%2,%3}, [%4];"
                 : "=r"(r[0]), "=r"(r[1]), "=r"(r[2]), "=r"(r[3]) : "r"(addr));
}
__device__ __forceinline__ void mma_f16(float* c, const uint32_t* a, const uint32_t* b)
{
    asm volatile("mma.sync.aligned.m16n8k16.row.col.f32.f16.f16.f32 "
                 "{%0,%1,%2,%3},{%4,%5,%6,%7},{%8,%9},{%0,%1,%2,%3};"
                 : "+f"(c[0]), "+f"(c[1]), "+f"(c[2]), "+f"(c[3])
                 : "r"(a[0]), "r"(a[1]), "r"(a[2]), "r"(a[3]), "r"(b[0]), "r"(b[1]));
}

// ============================================================================
// pure fp16 GEMM:  C = A*B^T (fp32 accum).
// BM=128, BN=64, BK=128 (256B smem rows, two-atom swizzle), 128 threads
// (4 warps: 4m x 1n, warp tile 32x64), 2-stage cp.async, 2 CTAs/SM.
// 128 MMAs per warp between barriers; 16 MMAs per 6 ldsm_x4 per ks step.
// MODE 0: Q -> fp16 hi/lo (Clo!=null), K/V -> fp16 hi (Clo==null); head-major.
// MODE 1: fp32 + bias.
// ============================================================================
#define STG_BYTES 49152       // AH 32768 | BH 16384
#define AH_OFF 0
#define BH_OFF 32768
#define GEMM_SMEM (2 * STG_BYTES)   // 98304

template<int MODE>
__device__ __forceinline__ void gemm_f16_body(
    const unsigned short* __restrict__ Ah,
    const unsigned short* __restrict__ Bh,
    float scale,
    unsigned short* __restrict__ Chi, unsigned short* __restrict__ Clo,
    const float* __restrict__ bias, float* __restrict__ C)
{
    extern __shared__ char dsm[];
    const uint32_t sbase = (uint32_t)__cvta_generic_to_shared(dsm);

    const int tid  = threadIdx.x;
    const int bm   = blockIdx.y * 128;
    const int bn   = blockIdx.x * 64;
    const int lane = tid & 31;
    const int wm   = tid >> 5;      // 0..3: 32-row band

    // 256B rows: chunk ch in 0..15; swizzled chunk = ((ch&7)^(row&7)) | (ch&8)
    auto load_stage = [&](int s, int k0) {
        const uint32_t sb = sbase + s * STG_BYTES;
#pragma unroll
        for (int t = 0; t < 16; t++) {
            int c   = tid + t * 128;        // 0..2047
            int row = c >> 4, ch = c & 15;
            size_t   gofs = (size_t)(bm + row) * DIM + k0 + ch * 8;
            uint32_t sw   = ((uint32_t)(((ch & 7) ^ (row & 7)) | (ch & 8))) << 4;
            cp16(sb + AH_OFF + row * 256 + sw, Ah + gofs);
        }
#pragma unroll
        for (int t = 0; t < 8; t++) {
            int c   = tid + t * 128;        // 0..1023
            int row = c >> 4, ch = c & 15;
            size_t   gofs = (size_t)(bn + row) * DIM + k0 + ch * 8;
            uint32_t sw   = ((uint32_t)(((ch & 7) ^ (row & 7)) | (ch & 8))) << 4;
            cp16(sb + BH_OFF + row * 256 + sw, Bh + gofs);
        }
    };

    float acc[2][8][4];
#pragma unroll
    for (int i = 0; i < 2; i++)
#pragma unroll
        for (int j = 0; j < 8; j++)
#pragma unroll
            for (int k = 0; k < 4; k++) acc[i][j][k] = 0.0f;

    const int a_r = wm * 32 + (lane & 15);                 // + mf*16
    const int a_k = (lane >> 4);
    const int a_x = a_r & 7;
    const int b_r = (lane & 7) + ((lane >> 4) << 3);       // + nf2*16
    const int b_k = (lane >> 3) & 1;

    load_stage(0, 0);
    cp_commit();

    constexpr int NIT = DIM / 128;   // 8
    for (int it = 0; it < NIT; ++it) {
        const int s = it & 1;
        if (it + 1 < NIT) {
            load_stage(s ^ 1, (it + 1) * 128);
            cp_commit();
            cp_wait<1>();
        } else {
            cp_wait<0>();
        }
        __syncthreads();

        const uint32_t sb = sbase + s * STG_BYTES;
#pragma unroll
        for (int ks = 0; ks < 8; ks++) {
            uint32_t ah[2][4], bh[4][4];
            const int cha = (ks << 1) | a_k;     // 0..15
            const int chb = (ks << 1) | b_k;
#pragma unroll
            for (int mf = 0; mf < 2; mf++) {
                uint32_t sw = ((uint32_t)(((cha & 7) ^ a_x) | (cha & 8))) << 4;
                ldsm_x4(ah[mf], sb + AH_OFF + (a_r + mf * 16) * 256 + sw);
            }
#pragma unroll
            for (int nf2 = 0; nf2 < 4; nf2++) {
                int r = b_r + nf2 * 16;
                uint32_t sw = ((uint32_t)(((chb & 7) ^ (r & 7)) | (chb & 8))) << 4;
                ldsm_x4(bh[nf2], sb + BH_OFF + r * 256 + sw);
            }
#pragma unroll
            for (int mf = 0; mf < 2; mf++)
#pragma unroll
                for (int nf = 0; nf < 8; nf++)
                    mma_f16(acc[mf][nf], ah[mf], &bh[nf >> 1][(nf & 1) * 2]);
        }
        __syncthreads();
    }

    // epilogue
#pragma unroll
    for (int mf = 0; mf < 2; mf++) {
        const int row0 = bm + wm * 32 + mf * 16 + (lane >> 2);
#pragma unroll
        for (int nf = 0; nf < 8; nf++) {
            const int col = bn + nf * 8 + (lane & 3) * 2;
            if (MODE == 0) {
                const int h = col >> 6, d = col & 63;
#pragma unroll
                for (int half = 0; half < 2; half++) {
                    const int row = row0 + half * 8;
                    const int b = row >> 11, t = row & 2047;
                    const size_t dst = (((size_t)(b * NHEADS + h) * SEQ) + t) * HDIM + d;
                    float f0 = acc[mf][nf][half * 2 + 0] * scale;
                    float f1 = acc[mf][nf][half * 2 + 1] * scale;
                    if (Clo) {
                        unsigned short h0, l0, h1, l1;
                        split1h(f0, h0, l0);
                        split1h(f1, h1, l1);
                        *(ushort2*)(Chi + dst) = make_ushort2(h0, h1);
                        *(ushort2*)(Clo + dst) = make_ushort2(l0, l1);
                    } else {
                        __half2 p = __floats2half2_rn(f0, f1);
                        *(uint32_t*)(Chi + dst) = *reinterpret_cast<uint32_t*>(&p);
                    }
                }
            } else {
                float b0 = bias[col], b1 = bias[col + 1];
                float2 v0 = make_float2(acc[mf][nf][0] + b0, acc[mf][nf][1] + b1);
                float2 v1 = make_float2(acc[mf][nf][2] + b0, acc[mf][nf][3] + b1);
                *(float2*)(C + (size_t)row0 * DIM + col)       = v0;
                *(float2*)(C + (size_t)(row0 + 8) * DIM + col) = v1;
            }
        }
    }
}

__global__ void __launch_bounds__(128, 2) gemm_qkv_f16()
{
    const int z = blockIdx.z;
    unsigned short* Chi = (z == 0) ? g_q_hi : (z == 1) ? g_k_hi : g_v_hi;
    unsigned short* Clo = (z == 0) ? g_q_lo : nullptr;
    const float scale = (z == 0) ? 0.125f : 1.0f;
    gemm_f16_body<0>(g_x_hi, g_w_hi + (size_t)z * DIM * DIM,
                     scale, Chi, Clo, nullptr, nullptr);
}

__global__ void __launch_bounds__(128, 2) gemm_out_f16(
    const float* __restrict__ bo, float* __restrict__ out)
{
    gemm_f16_body<1>(g_o_hi, g_w_hi + (size_t)3 * DIM * DIM,
                     1.0f, nullptr, nullptr, bo, out);
}

// ============================================================================
// Tensor-core flash attention (causal).
// S = Qh*Kh + Ql*Kh (Q 2-term).  O = Ph*Vh (P 1-term).
// BQ=64: 128 threads (4 warps), BK=64, 3-stage KV ring, 64KB smem.
// ============================================================================
#define ATT_QH 0
#define ATT_QL 8192
#define ATT_STG0 16384
#define ATT_STG_BYTES 16384       // KH 8K | VH 8K
#define ATT_KH 0
#define ATT_VH 8192
#define ATT_NSTG 3
#define ATT_SMEM (ATT_STG0 + ATT_NSTG * ATT_STG_BYTES)   // 65536

#define NEG_INF __int_as_float(0xff800000)

__global__ void __launch_bounds__(128, 1) attn_mma_kernel()
{
    extern __shared__ char dsm[];
    const uint32_t sbase = (uint32_t)__cvta_generic_to_shared(dsm);

    const int tid  = threadIdx.x;
    const int lane = tid & 31;
    const int w    = tid >> 5;
    const int qb   = (gridDim.x - 1) - blockIdx.x;
    const int h    = blockIdx.y;
    const int b    = blockIdx.z;
    const int q0   = qb * 64;

    const size_t head = (size_t)(b * NHEADS + h) * SEQ * HDIM;
    const unsigned short* Qh = g_q_hi + head;
    const unsigned short* Ql = g_q_lo + head;
    const unsigned short* Kh = g_k_hi + head;
    const unsigned short* Vh = g_v_hi + head;

#pragma unroll
    for (int t = 0; t < 4; t++) {
        int c = tid + t * 128;
        int row = c >> 3, ch = c & 7;
        size_t   g = (size_t)(q0 + row) * HDIM + ch * 8;
        uint32_t sofs = row * 128 + ((ch ^ (row & 7)) << 4);
        cp16(sbase + ATT_QH + sofs, Qh + g);
        cp16(sbase + ATT_QL + sofs, Ql + g);
    }

    auto load_kv = [&](int s, int k0) {
        const uint32_t st = sbase + ATT_STG0 + s * ATT_STG_BYTES;
#pragma unroll
        for (int t = 0; t < 4; t++) {
            int c = tid + t * 128;
            int row = c >> 3, ch = c & 7;
            size_t   g = (size_t)(k0 + row) * HDIM + ch * 8;
            uint32_t sofs = row * 128 + ((ch ^ (row & 7)) << 4);
            cp16(st + ATT_KH + sofs, Kh + g);
            cp16(st + ATT_VH + sofs, Vh + g);
        }
    };

    const int kmax = qb;

    load_kv(0, 0);
    cp_commit();
    if (kmax >= 1) {
        load_kv(1, 64);
        cp_commit();
    }

    const int a_r = w * 16 + (lane & 15);
    const int a_k = lane >> 4;
    const int a_x = a_r & 7;
    const int k_r = (lane & 7) + ((lane >> 4) << 3);
    const int k_k = (lane >> 3) & 1;
    const int v_r = (lane & 7) + (((lane >> 3) & 1) << 3);
    const int v_c = lane >> 4;

    uint32_t qh[4][4], ql[4][4];

    float m_run[2] = {NEG_INF, NEG_INF};
    float l_run[2] = {0.0f, 0.0f};
    float acc_o[8][4];
#pragma unroll
    for (int i = 0; i < 8; i++)
#pragma unroll
        for (int j = 0; j < 4; j++) acc_o[i][j] = 0.0f;

    int s = 0;
    for (int kb = 0; kb <= kmax; kb++) {
        const int k0 = kb * 64;
        if (kb + 2 <= kmax) {
            load_kv((s + 2) % ATT_NSTG, (kb + 2) * 64);
            cp_commit();
            cp_wait<2>();
        } else if (kb + 1 <= kmax) {
            cp_wait<1>();
        } else {
            cp_wait<0>();
        }
        __syncthreads();

        if (kb == 0) {
#pragma unroll
            for (int ks = 0; ks < 4; ks++) {
                uint32_t off = a_r * 128 + ((((ks << 1) | a_k) ^ a_x) << 4);
                ldsm_x4(qh[ks], sbase + ATT_QH + off);
                ldsm_x4(ql[ks], sbase + ATT_QL + off);
            }
        }

        const uint32_t st = sbase + ATT_STG0 + s * ATT_STG_BYTES;

        float s_acc[8][4];
#pragma unroll
        for (int i = 0; i < 8; i++)
#pragma unroll
            for (int j = 0; j < 4; j++) s_acc[i][j] = 0.0f;

#pragma unroll
        for (int ks = 0; ks < 4; ks++) {
            uint32_t bh[4][4];
#pragma unroll
            for (int nf2 = 0; nf2 < 4; nf2++) {
                int r = k_r + nf2 * 16;
                uint32_t off = r * 128 + ((((ks << 1) | k_k) ^ (r & 7)) << 4);
                ldsm_x4(bh[nf2], st + ATT_KH + off);
            }
#pragma unroll
            for (int nf = 0; nf < 8; nf++)
                mma_f16(s_acc[nf], qh[ks], &bh[nf >> 1][(nf & 1) * 2]);
#pragma unroll
            for (int nf = 0; nf < 8; nf++)
                mma_f16(s_acc[nf], ql[ks], &bh[nf >> 1][(nf & 1) * 2]);
        }

        if (kb == qb) {
            const int qpos0 = q0 + w * 16 + (lane >> 2);
            const int kbase = k0 + (lane & 3) * 2;
#pragma unroll
            for (int nf = 0; nf < 8; nf++) {
                const int kp = kbase + nf * 8;
                if (kp     > qpos0)     s_acc[nf][0] = NEG_INF;
                if (kp + 1 > qpos0)     s_acc[nf][1] = NEG_INF;
                if (kp     > qpos0 + 8) s_acc[nf][2] = NEG_INF;
                if (kp + 1 > qpos0 + 8) s_acc[nf][3] = NEG_INF;
            }
        }

#pragma unroll
        for (int half = 0; half < 2; half++) {
            float mx = NEG_INF;
#pragma unroll
            for (int nf = 0; nf < 8; nf++)
                mx = fmaxf(mx, fmaxf(s_acc[nf][half * 2], s_acc[nf][half * 2 + 1]));
            mx = fmaxf(mx, __shfl_xor_sync(0xffffffffu, mx, 1));
            mx = fmaxf(mx, __shfl_xor_sync(0xffffffffu, mx, 2));

            const float mnew  = fmaxf(m_run[half], mx);
            const float alpha = __expf(m_run[half] - mnew);
            m_run[half] = mnew;

            float sum = 0.0f;
#pragma unroll
            for (int nf = 0; nf < 8; nf++) {
                float p0 = __expf(s_acc[nf][half * 2]     - mnew);
                float p1 = __expf(s_acc[nf][half * 2 + 1] - mnew);
                s_acc[nf][half * 2]     = p0;
                s_acc[nf][half * 2 + 1] = p1;
                sum += p0 + p1;
            }
            sum += __shfl_xor_sync(0xffffffffu, sum, 1);
            sum += __shfl_xor_sync(0xffffffffu, sum, 2);
            l_run[half] = l_run[half] * alpha + sum;

#pragma unroll
            for (int dn = 0; dn < 8; dn++) {
                acc_o[dn][half * 2]     *= alpha;
                acc_o[dn][half * 2 + 1] *= alpha;
            }
        }

        // ---- O += P V, P 1-term fp16 ----
#pragma unroll
        for (int kc = 0; kc < 4; kc++) {
            uint32_t ah[4];
#pragma unroll
            for (int q = 0; q < 2; q++) {
                const float* sc = s_acc[2 * kc + q];
                ah[q * 2 + 0] = h2pack(sc[0], sc[1]);
                ah[q * 2 + 1] = h2pack(sc[2], sc[3]);
            }
            uint32_t vh[4][4];
#pragma unroll
            for (int dg = 0; dg < 4; dg++) {
                int r = v_r + kc * 16;
                int ch = v_c + dg * 2;
                uint32_t off = r * 128 + ((ch ^ (r & 7)) << 4);
                ldsm_x4_t(vh[dg], st + ATT_VH + off);
            }
#pragma unroll
            for (int dg = 0; dg < 4; dg++)
#pragma unroll
                for (int q = 0; q < 2; q++)
                    mma_f16(acc_o[dg * 2 + q], ah, &vh[dg][q * 2]);
        }
        __syncthreads();
        s = (s + 1) % ATT_NSTG;
    }

    // ---- epilogue: normalize, store fp16, token-major ----
    const float inv0 = 1.0f / l_run[0];
    const float inv1 = 1.0f / l_run[1];
    const int row0 = q0 + w * 16 + (lane >> 2);
    const size_t tok0 = (size_t)(b * SEQ + row0) * DIM + h * HDIM;
    const size_t tok1 = tok0 + 8 * DIM;
#pragma unroll
    for (int dn = 0; dn < 8; dn++) {
        const int d = dn * 8 + (lane & 3) * 2;
        __half2 p0 = __floats2half2_rn(acc_o[dn][0] * inv0, acc_o[dn][1] * inv0);
        __half2 p1 = __floats2half2_rn(acc_o[dn][2] * inv1, acc_o[dn][3] * inv1);
        *(uint32_t*)(g_o_hi + tok0 + d) = *reinterpret_cast<uint32_t*>(&p0);
        *(uint32_t*)(g_o_hi + tok1 + d) = *reinterpret_cast<uint32_t*>(&p1);
    }
}

// ============================================================================
// launch
// ============================================================================
extern "C" void kernel_launch(void* const* d_in, const int* in_sizes, int n_in,
                              void* d_out, int out_size)
{
    const float* x  = (const float*)d_in[0];
    const float* Wq = (const float*)d_in[1];
    const float* Wk = (const float*)d_in[2];
    const float* Wv = (const float*)d_in[3];
    const float* Wo = (const float*)d_in[4];
    const float* bo = (const float*)d_in[5];
    float* out = (float*)d_out;

    cudaFuncSetAttribute(gemm_qkv_f16,    cudaFuncAttributeMaxDynamicSharedMemorySize, GEMM_SMEM);
    cudaFuncSetAttribute(gemm_out_f16,    cudaFuncAttributeMaxDynamicSharedMemorySize, GEMM_SMEM);
    cudaFuncSetAttribute(attn_mma_kernel, cudaFuncAttributeMaxDynamicSharedMemorySize, ATT_SMEM);

    // fused fp16 conversions (x and W)
    split_all_kernel<<<2048, 256>>>(x, Wq, Wk, Wv, Wo);

    // QKV projections (1-term fp16) -> Q fp16 hi/lo (pre-scaled), K/V fp16 hi
    dim3 gridQKV(DIM / 64, MTOT / 128, 3);
    gemm_qkv_f16<<<gridQKV, 128, GEMM_SMEM>>>();

    // flash attention: S 2-term, PV 1-term
    dim3 gridAtt(SEQ / 64, NHEADS, BATCH);
    attn_mma_kernel<<<gridAtt, 128, ATT_SMEM>>>();

    // output projection + bias (1-term fp16)
    dim3 gridOut(DIM / 64, MTOT / 128);
    gemm_out_f16<<<gridOut, 128, GEMM_SMEM>>>(bo, out);
}

// round 17
// speedup vs baseline: 2.2739x; 1.1161x over previous
#include <cuda_runtime.h>
#include <cuda_fp16.h>
#include <math.h>
#include <stdint.h>

#define DIM    1024
#define NHEADS 16
#define HDIM   64
#define BATCH  2
#define SEQ    2048
#define MTOT   (BATCH * SEQ)   // 4096

// ---------------- scratch (static device globals; no allocation) ----------------
__device__ unsigned short g_x_hi[MTOT * DIM];          // x fp16
__device__ unsigned short g_w_hi[4 * DIM * DIM];       // Wq,Wk,Wv,Wo fp16
// Q/K/V fp16, head-major [B][H][T][D] (Q pre-scaled by 1/8)
__device__ unsigned short g_q_hi[MTOT * DIM];
__device__ unsigned short g_k_hi[MTOT * DIM];
__device__ unsigned short g_v_hi[MTOT * DIM];
// attention output, token-major [MTOT][DIM], fp16
__device__ unsigned short g_o_hi[MTOT * DIM];

// ============================================================================
// helpers (fp16)
// ============================================================================
__device__ __forceinline__ uint32_t h2pack(float a, float b)
{
    __half2 t = __floats2half2_rn(a, b);
    return *reinterpret_cast<uint32_t*>(&t);
}

// fused convert: x -> fp16 (1024 blocks), W -> fp16 (1024 blocks); 4 float4/thread.
__global__ void split_all_kernel(const float* __restrict__ x,
                                 const float* __restrict__ Wq,
                                 const float* __restrict__ Wk,
                                 const float* __restrict__ Wv,
                                 const float* __restrict__ Wo)
{
    const int blk = blockIdx.x;
    if (blk < 1024) {
        int base = blk * 1024 + threadIdx.x;
#pragma unroll
        for (int j = 0; j < 4; j++) {
            int i = base + j * 256;
            float4 v = ((const float4*)x)[i];
            __half2 p0 = __floats2half2_rn(v.x, v.y);
            __half2 p1 = __floats2half2_rn(v.z, v.w);
            ((uint2*)g_x_hi)[i] = make_uint2(*reinterpret_cast<uint32_t*>(&p0),
                                             *reinterpret_cast<uint32_t*>(&p1));
        }
    } else {
        int wbase = (blk - 1024) * 1024 + threadIdx.x;
#pragma unroll
        for (int j = 0; j < 4; j++) {
            int widx = wbase + j * 256;
            int z = widx >> 18;
            int i = widx & 262143;
            const float* w = (z == 0) ? Wq : (z == 1) ? Wk : (z == 2) ? Wv : Wo;
            float4 v = ((const float4*)w)[i];
            __half2 p0 = __floats2half2_rn(v.x, v.y);
            __half2 p1 = __floats2half2_rn(v.z, v.w);
            ((uint2*)g_w_hi)[(size_t)z * 262144 + i] =
                make_uint2(*reinterpret_cast<uint32_t*>(&p0),
                           *reinterpret_cast<uint32_t*>(&p1));
        }
    }
}

// ============================================================================
// async / mma primitives
// ============================================================================
__device__ __forceinline__ void cp16(uint32_t dst, const void* src)
{
    asm volatile("cp.async.cg.shared.global [%0], [%1], 16;\n" :: "r"(dst), "l"(src));
}
__device__ __forceinline__ void cp_commit()
{
    asm volatile("cp.async.commit_group;\n");
}
template<int N> __device__ __forceinline__ void cp_wait()
{
    asm volatile("cp.async.wait_group %0;\n" :: "n"(N));
}
__device__ __forceinline__ void ldsm_x4(uint32_t* r, uint32_t addr)
{
    asm volatile("ldmatrix.sync.aligned.m8n8.x4.shared.b16 {%0,%1,%2,%3}, [%4];"
                 : "=r"(r[0]), "=r"(r[1]), "=r"(r[2]), "=r"(r[3]) : "r"(addr));
}
__device__ __forceinline__ void ldsm_x4_t(uint32_t* r, uint32_t addr)
{
    asm volatile("ldmatrix.sync.aligned.m8n8.x4.trans.shared.b16 {%0,%1,%2,%3}, [%4];"
                 : "=r"(r[0]), "=r"(r[1]), "=r"(r[2]), "=r"(r[3]) : "r"(addr));
}
__device__ __forceinline__ void mma_f16(float* c, const uint32_t* a, const uint32_t* b)
{
    asm volatile("mma.sync.aligned.m16n8k16.row.col.f32.f16.f16.f32 "
                 "{%0,%1,%2,%3},{%4,%5,%6,%7},{%8,%9},{%0,%1,%2,%3};"
                 : "+f"(c[0]), "+f"(c[1]), "+f"(c[2]), "+f"(c[3])
                 : "r"(a[0]), "r"(a[1]), "r"(a[2]), "r"(a[3]), "r"(b[0]), "r"(b[1]));
}

// ============================================================================
// pure fp16 GEMM:  C = A*B^T (fp32 accum) — R16 config.
// BM=128, BN=64, BK=128 (256B rows, two-atom swizzle), 128 threads
// (4 warps: 4m x 1n, warp tile 32x64), 2-stage cp.async, 2 CTAs/SM.
// MODE 0: fp16 store, head-major scatter.  MODE 1: fp32 + bias.
// ============================================================================
#define STG_BYTES 49152       // AH 32768 | BH 16384
#define AH_OFF 0
#define BH_OFF 32768
#define GEMM_SMEM (2 * STG_BYTES)   // 98304

template<int MODE>
__device__ __forceinline__ void gemm_f16_body(
    const unsigned short* __restrict__ Ah,
    const unsigned short* __restrict__ Bh,
    float scale,
    unsigned short* __restrict__ Chi,
    const float* __restrict__ bias, float* __restrict__ C)
{
    extern __shared__ char dsm[];
    const uint32_t sbase = (uint32_t)__cvta_generic_to_shared(dsm);

    const int tid  = threadIdx.x;
    const int bm   = blockIdx.y * 128;
    const int bn   = blockIdx.x * 64;
    const int lane = tid & 31;
    const int wm   = tid >> 5;      // 0..3: 32-row band

    auto load_stage = [&](int s, int k0) {
        const uint32_t sb = sbase + s * STG_BYTES;
#pragma unroll
        for (int t = 0; t < 16; t++) {
            int c   = tid + t * 128;        // 0..2047
            int row = c >> 4, ch = c & 15;
            size_t   gofs = (size_t)(bm + row) * DIM + k0 + ch * 8;
            uint32_t sw   = ((uint32_t)(((ch & 7) ^ (row & 7)) | (ch & 8))) << 4;
            cp16(sb + AH_OFF + row * 256 + sw, Ah + gofs);
        }
#pragma unroll
        for (int t = 0; t < 8; t++) {
            int c   = tid + t * 128;        // 0..1023
            int row = c >> 4, ch = c & 15;
            size_t   gofs = (size_t)(bn + row) * DIM + k0 + ch * 8;
            uint32_t sw   = ((uint32_t)(((ch & 7) ^ (row & 7)) | (ch & 8))) << 4;
            cp16(sb + BH_OFF + row * 256 + sw, Bh + gofs);
        }
    };

    float acc[2][8][4];
#pragma unroll
    for (int i = 0; i < 2; i++)
#pragma unroll
        for (int j = 0; j < 8; j++)
#pragma unroll
            for (int k = 0; k < 4; k++) acc[i][j][k] = 0.0f;

    const int a_r = wm * 32 + (lane & 15);
    const int a_k = (lane >> 4);
    const int a_x = a_r & 7;
    const int b_r = (lane & 7) + ((lane >> 4) << 3);
    const int b_k = (lane >> 3) & 1;

    load_stage(0, 0);
    cp_commit();

    constexpr int NIT = DIM / 128;   // 8
    for (int it = 0; it < NIT; ++it) {
        const int s = it & 1;
        if (it + 1 < NIT) {
            load_stage(s ^ 1, (it + 1) * 128);
            cp_commit();
            cp_wait<1>();
        } else {
            cp_wait<0>();
        }
        __syncthreads();

        const uint32_t sb = sbase + s * STG_BYTES;
#pragma unroll
        for (int ks = 0; ks < 8; ks++) {
            uint32_t ah[2][4], bh[4][4];
            const int cha = (ks << 1) | a_k;
            const int chb = (ks << 1) | b_k;
#pragma unroll
            for (int mf = 0; mf < 2; mf++) {
                uint32_t sw = ((uint32_t)(((cha & 7) ^ a_x) | (cha & 8))) << 4;
                ldsm_x4(ah[mf], sb + AH_OFF + (a_r + mf * 16) * 256 + sw);
            }
#pragma unroll
            for (int nf2 = 0; nf2 < 4; nf2++) {
                int r = b_r + nf2 * 16;
                uint32_t sw = ((uint32_t)(((chb & 7) ^ (r & 7)) | (chb & 8))) << 4;
                ldsm_x4(bh[nf2], sb + BH_OFF + r * 256 + sw);
            }
#pragma unroll
            for (int mf = 0; mf < 2; mf++)
#pragma unroll
                for (int nf = 0; nf < 8; nf++)
                    mma_f16(acc[mf][nf], ah[mf], &bh[nf >> 1][(nf & 1) * 2]);
        }
        __syncthreads();
    }

    // epilogue
#pragma unroll
    for (int mf = 0; mf < 2; mf++) {
        const int row0 = bm + wm * 32 + mf * 16 + (lane >> 2);
#pragma unroll
        for (int nf = 0; nf < 8; nf++) {
            const int col = bn + nf * 8 + (lane & 3) * 2;
            if (MODE == 0) {
                const int h = col >> 6, d = col & 63;
#pragma unroll
                for (int half = 0; half < 2; half++) {
                    const int row = row0 + half * 8;
                    const int b = row >> 11, t = row & 2047;
                    const size_t dst = (((size_t)(b * NHEADS + h) * SEQ) + t) * HDIM + d;
                    __half2 p = __floats2half2_rn(acc[mf][nf][half * 2 + 0] * scale,
                                                  acc[mf][nf][half * 2 + 1] * scale);
                    *(uint32_t*)(Chi + dst) = *reinterpret_cast<uint32_t*>(&p);
                }
            } else {
                float b0 = bias[col], b1 = bias[col + 1];
                float2 v0 = make_float2(acc[mf][nf][0] + b0, acc[mf][nf][1] + b1);
                float2 v1 = make_float2(acc[mf][nf][2] + b0, acc[mf][nf][3] + b1);
                *(float2*)(C + (size_t)row0 * DIM + col)       = v0;
                *(float2*)(C + (size_t)(row0 + 8) * DIM + col) = v1;
            }
        }
    }
}

__global__ void __launch_bounds__(128, 2) gemm_qkv_f16()
{
    const int z = blockIdx.z;
    unsigned short* Chi = (z == 0) ? g_q_hi : (z == 1) ? g_k_hi : g_v_hi;
    const float scale = (z == 0) ? 0.125f : 1.0f;
    gemm_f16_body<0>(g_x_hi, g_w_hi + (size_t)z * DIM * DIM,
                     scale, Chi, nullptr, nullptr);
}

__global__ void __launch_bounds__(128, 2) gemm_out_f16(
    const float* __restrict__ bo, float* __restrict__ out)
{
    gemm_f16_body<1>(g_o_hi, g_w_hi + (size_t)3 * DIM * DIM,
                     1.0f, nullptr, bo, out);
}

// ============================================================================
// Tensor-core flash attention (causal), pure fp16 operands (fp32 accum).
// S = Qh*Kh (1-term).  O = Ph*Vh (1-term).
// BQ=64: 128 threads (4 warps), BK=64, 3-stage KV ring, 56KB smem (3 CTAs/SM).
// ============================================================================
#define ATT_QH 0
#define ATT_STG0 8192
#define ATT_STG_BYTES 16384       // KH 8K | VH 8K
#define ATT_KH 0
#define ATT_VH 8192
#define ATT_NSTG 3
#define ATT_SMEM (ATT_STG0 + ATT_NSTG * ATT_STG_BYTES)   // 57344

#define NEG_INF __int_as_float(0xff800000)

__global__ void __launch_bounds__(128, 3) attn_mma_kernel()
{
    extern __shared__ char dsm[];
    const uint32_t sbase = (uint32_t)__cvta_generic_to_shared(dsm);

    const int tid  = threadIdx.x;
    const int lane = tid & 31;
    const int w    = tid >> 5;
    const int qb   = (gridDim.x - 1) - blockIdx.x;
    const int h    = blockIdx.y;
    const int b    = blockIdx.z;
    const int q0   = qb * 64;

    const size_t head = (size_t)(b * NHEADS + h) * SEQ * HDIM;
    const unsigned short* Qh = g_q_hi + head;
    const unsigned short* Kh = g_k_hi + head;
    const unsigned short* Vh = g_v_hi + head;

#pragma unroll
    for (int t = 0; t < 4; t++) {
        int c = tid + t * 128;
        int row = c >> 3, ch = c & 7;
        size_t   g = (size_t)(q0 + row) * HDIM + ch * 8;
        uint32_t sofs = row * 128 + ((ch ^ (row & 7)) << 4);
        cp16(sbase + ATT_QH + sofs, Qh + g);
    }

    auto load_kv = [&](int s, int k0) {
        const uint32_t st = sbase + ATT_STG0 + s * ATT_STG_BYTES;
#pragma unroll
        for (int t = 0; t < 4; t++) {
            int c = tid + t * 128;
            int row = c >> 3, ch = c & 7;
            size_t   g = (size_t)(k0 + row) * HDIM + ch * 8;
            uint32_t sofs = row * 128 + ((ch ^ (row & 7)) << 4);
            cp16(st + ATT_KH + sofs, Kh + g);
            cp16(st + ATT_VH + sofs, Vh + g);
        }
    };

    const int kmax = qb;

    load_kv(0, 0);
    cp_commit();
    if (kmax >= 1) {
        load_kv(1, 64);
        cp_commit();
    }

    const int a_r = w * 16 + (lane & 15);
    const int a_k = lane >> 4;
    const int a_x = a_r & 7;
    const int k_r = (lane & 7) + ((lane >> 4) << 3);
    const int k_k = (lane >> 3) & 1;
    const int v_r = (lane & 7) + (((lane >> 3) & 1) << 3);
    const int v_c = lane >> 4;

    uint32_t qh[4][4];

    float m_run[2] = {NEG_INF, NEG_INF};
    float l_run[2] = {0.0f, 0.0f};
    float acc_o[8][4];
#pragma unroll
    for (int i = 0; i < 8; i++)
#pragma unroll
        for (int j = 0; j < 4; j++) acc_o[i][j] = 0.0f;

    int s = 0;
    for (int kb = 0; kb <= kmax; kb++) {
        const int k0 = kb * 64;
        if (kb + 2 <= kmax) {
            load_kv((s + 2) % ATT_NSTG, (kb + 2) * 64);
            cp_commit();
            cp_wait<2>();
        } else if (kb + 1 <= kmax) {
            cp_wait<1>();
        } else {
            cp_wait<0>();
        }
        __syncthreads();

        if (kb == 0) {
#pragma unroll
            for (int ks = 0; ks < 4; ks++) {
                uint32_t off = a_r * 128 + ((((ks << 1) | a_k) ^ a_x) << 4);
                ldsm_x4(qh[ks], sbase + ATT_QH + off);
            }
        }

        const uint32_t st = sbase + ATT_STG0 + s * ATT_STG_BYTES;

        float s_acc[8][4];
#pragma unroll
        for (int i = 0; i < 8; i++)
#pragma unroll
            for (int j = 0; j < 4; j++) s_acc[i][j] = 0.0f;

#pragma unroll
        for (int ks = 0; ks < 4; ks++) {
            uint32_t bh[4][4];
#pragma unroll
            for (int nf2 = 0; nf2 < 4; nf2++) {
                int r = k_r + nf2 * 16;
                uint32_t off = r * 128 + ((((ks << 1) | k_k) ^ (r & 7)) << 4);
                ldsm_x4(bh[nf2], st + ATT_KH + off);
            }
#pragma unroll
            for (int nf = 0; nf < 8; nf++)
                mma_f16(s_acc[nf], qh[ks], &bh[nf >> 1][(nf & 1) * 2]);
        }

        if (kb == qb) {
            const int qpos0 = q0 + w * 16 + (lane >> 2);
            const int kbase = k0 + (lane & 3) * 2;
#pragma unroll
            for (int nf = 0; nf < 8; nf++) {
                const int kp = kbase + nf * 8;
                if (kp     > qpos0)     s_acc[nf][0] = NEG_INF;
                if (kp + 1 > qpos0)     s_acc[nf][1] = NEG_INF;
                if (kp     > qpos0 + 8) s_acc[nf][2] = NEG_INF;
                if (kp + 1 > qpos0 + 8) s_acc[nf][3] = NEG_INF;
            }
        }

#pragma unroll
        for (int half = 0; half < 2; half++) {
            float mx = NEG_INF;
#pragma unroll
            for (int nf = 0; nf < 8; nf++)
                mx = fmaxf(mx, fmaxf(s_acc[nf][half * 2], s_acc[nf][half * 2 + 1]));
            mx = fmaxf(mx, __shfl_xor_sync(0xffffffffu, mx, 1));
            mx = fmaxf(mx, __shfl_xor_sync(0xffffffffu, mx, 2));

            const float mnew  = fmaxf(m_run[half], mx);
            const float alpha = __expf(m_run[half] - mnew);
            m_run[half] = mnew;

            float sum = 0.0f;
#pragma unroll
            for (int nf = 0; nf < 8; nf++) {
                float p0 = __expf(s_acc[nf][half * 2]     - mnew);
                float p1 = __expf(s_acc[nf][half * 2 + 1] - mnew);
                s_acc[nf][half * 2]     = p0;
                s_acc[nf][half * 2 + 1] = p1;
                sum += p0 + p1;
            }
            sum += __shfl_xor_sync(0xffffffffu, sum, 1);
            sum += __shfl_xor_sync(0xffffffffu, sum, 2);
            l_run[half] = l_run[half] * alpha + sum;

#pragma unroll
            for (int dn = 0; dn < 8; dn++) {
                acc_o[dn][half * 2]     *= alpha;
                acc_o[dn][half * 2 + 1] *= alpha;
            }
        }

        // ---- O += P V, P 1-term fp16 ----
#pragma unroll
        for (int kc = 0; kc < 4; kc++) {
            uint32_t ah[4];
#pragma unroll
            for (int q = 0; q < 2; q++) {
                const float* sc = s_acc[2 * kc + q];
                ah[q * 2 + 0] = h2pack(sc[0], sc[1]);
                ah[q * 2 + 1] = h2pack(sc[2], sc[3]);
            }
            uint32_t vh[4][4];
#pragma unroll
            for (int dg = 0; dg < 4; dg++) {
                int r = v_r + kc * 16;
                int ch = v_c + dg * 2;
                uint32_t off = r * 128 + ((ch ^ (r & 7)) << 4);
                ldsm_x4_t(vh[dg], st + ATT_VH + off);
            }
#pragma unroll
            for (int dg = 0; dg < 4; dg++)
#pragma unroll
                for (int q = 0; q < 2; q++)
                    mma_f16(acc_o[dg * 2 + q], ah, &vh[dg][q * 2]);
        }
        __syncthreads();
        s = (s + 1) % ATT_NSTG;
    }

    // ---- epilogue: normalize, store fp16, token-major ----
    const float inv0 = 1.0f / l_run[0];
    const float inv1 = 1.0f / l_run[1];
    const int row0 = q0 + w * 16 + (lane >> 2);
    const size_t tok0 = (size_t)(b * SEQ + row0) * DIM + h * HDIM;
    const size_t tok1 = tok0 + 8 * DIM;
#pragma unroll
    for (int dn = 0; dn < 8; dn++) {
        const int d = dn * 8 + (lane & 3) * 2;
        __half2 p0 = __floats2half2_rn(acc_o[dn][0] * inv0, acc_o[dn][1] * inv0);
        __half2 p1 = __floats2half2_rn(acc_o[dn][2] * inv1, acc_o[dn][3] * inv1);
        *(uint32_t*)(g_o_hi + tok0 + d) = *reinterpret_cast<uint32_t*>(&p0);
        *(uint32_t*)(g_o_hi + tok1 + d) = *reinterpret_cast<uint32_t*>(&p1);
    }
}

// ============================================================================
// launch
// ============================================================================
extern "C" void kernel_launch(void* const* d_in, const int* in_sizes, int n_in,
                              void* d_out, int out_size)
{
    const float* x  = (const float*)d_in[0];
    const float* Wq = (const float*)d_in[1];
    const float* Wk = (const float*)d_in[2];
    const float* Wv = (const float*)d_in[3];
    const float* Wo = (const float*)d_in[4];
    const float* bo = (const float*)d_in[5];
    float* out = (float*)d_out;

    cudaFuncSetAttribute(gemm_qkv_f16,    cudaFuncAttributeMaxDynamicSharedMemorySize, GEMM_SMEM);
    cudaFuncSetAttribute(gemm_out_f16,    cudaFuncAttributeMaxDynamicSharedMemorySize, GEMM_SMEM);
    cudaFuncSetAttribute(attn_mma_kernel, cudaFuncAttributeMaxDynamicSharedMemorySize, ATT_SMEM);

    // fused fp16 conversions (x and W)
    split_all_kernel<<<2048, 256>>>(x, Wq, Wk, Wv, Wo);

    // QKV projections (1-term fp16) -> Q/K/V fp16, head-major (Q pre-scaled)
    dim3 gridQKV(DIM / 64, MTOT / 128, 3);
    gemm_qkv_f16<<<gridQKV, 128, GEMM_SMEM>>>();

    // flash attention: S 1-term, PV 1-term
    dim3 gridAtt(SEQ / 64, NHEADS, BATCH);
    attn_mma_kernel<<<gridAtt, 128, ATT_SMEM>>>();

    // output projection + bias (1-term fp16)
    dim3 gridOut(DIM / 64, MTOT / 128);
    gemm_out_f16<<<gridOut, 128, GEMM_SMEM>>>(bo, out);
}